// round 13
// baseline (speedup 1.0000x reference)
#include <cuda_runtime.h>
#include <cuda_bf16.h>
#include <cstdint>
#include <cstddef>

// Problem constants
#define BB 2
#define LL 2048
#define EE 2048
#define HQ 16
#define HKV 2
#define DD 128
#define MROWS (BB*LL)   // 4096

// ---------------------------------------------------------------------------
// Scratch (device globals — no allocations allowed)
// ---------------------------------------------------------------------------
__device__ float g_q[(size_t)MROWS * HQ * DD];     // Q fp32 pre-rope; reused as attn out fp32
__device__ float g_k[(size_t)MROWS * HKV * DD];    // K fp32 pre-rope

// bf16 split Q (post-rope) / K / V for attention
__device__ __nv_bfloat16 g_ah[(size_t)MROWS * HQ * DD];
__device__ __nv_bfloat16 g_al[(size_t)MROWS * HQ * DD];
__device__ __nv_bfloat16 g_kh2[(size_t)MROWS * HKV * DD];
__device__ __nv_bfloat16 g_kl2[(size_t)MROWS * HKV * DD];
__device__ __nv_bfloat16 g_vh2[(size_t)MROWS * HKV * DD];
__device__ __nv_bfloat16 g_vl2[(size_t)MROWS * HKV * DD];

// int8 hi/lo activations (X, then attn-out) + per-row scales
__device__ signed char g_x8h[(size_t)MROWS * EE];
__device__ signed char g_x8l[(size_t)MROWS * EE];
__device__ float g_xs[MROWS];
// int8 hi/lo transposed weights [N][K] + per-col scales
__device__ signed char g_wq8h[(size_t)(HQ*DD) * EE];
__device__ signed char g_wq8l[(size_t)(HQ*DD) * EE];
__device__ float g_wqs[HQ*DD];
__device__ signed char g_wk8h[(size_t)(HKV*DD) * EE];
__device__ signed char g_wk8l[(size_t)(HKV*DD) * EE];
__device__ float g_wks[HKV*DD];
__device__ signed char g_wv8h[(size_t)(HKV*DD) * EE];
__device__ signed char g_wv8l[(size_t)(HKV*DD) * EE];
__device__ float g_wvs[HKV*DD];
__device__ signed char g_wo8h[(size_t)EE * (HQ*DD)];
__device__ signed char g_wo8l[(size_t)EE * (HQ*DD)];
__device__ float g_wos[EE];

// ---------------------------------------------------------------------------
// PTX helpers
// ---------------------------------------------------------------------------
__device__ __forceinline__ uint32_t smem_u32(const void* p) {
    uint32_t a;
    asm("{ .reg .u64 t; cvta.to.shared.u64 t, %1; cvt.u32.u64 %0, t; }"
        : "=r"(a) : "l"(p));
    return a;
}

__device__ __forceinline__ void cpa16(uint32_t d, const void* s) {
    asm volatile("cp.async.cg.shared.global [%0], [%1], 16;" :: "r"(d), "l"(s));
}
#define CP_COMMIT() asm volatile("cp.async.commit_group;")
#define CP_WAIT(n)  asm volatile("cp.async.wait_group %0;" :: "n"(n))

__device__ __forceinline__ void ldmx4(uint32_t a, uint32_t r[4]) {
    asm volatile("ldmatrix.sync.aligned.m8n8.x4.shared.b16 {%0,%1,%2,%3}, [%4];"
                 : "=r"(r[0]), "=r"(r[1]), "=r"(r[2]), "=r"(r[3]) : "r"(a));
}
__device__ __forceinline__ void ldmx4t(uint32_t a, uint32_t r[4]) {
    asm volatile("ldmatrix.sync.aligned.m8n8.x4.trans.shared.b16 {%0,%1,%2,%3}, [%4];"
                 : "=r"(r[0]), "=r"(r[1]), "=r"(r[2]), "=r"(r[3]) : "r"(a));
}

__device__ __forceinline__ void mma16816(float c[4], const uint32_t a[4],
                                         const uint32_t b[2]) {
    asm volatile(
        "mma.sync.aligned.m16n8k16.row.col.f32.bf16.bf16.f32 "
        "{%0,%1,%2,%3}, {%4,%5,%6,%7}, {%8,%9}, {%0,%1,%2,%3};"
        : "+f"(c[0]), "+f"(c[1]), "+f"(c[2]), "+f"(c[3])
        : "r"(a[0]), "r"(a[1]), "r"(a[2]), "r"(a[3]), "r"(b[0]), "r"(b[1]));
}

__device__ __forceinline__ void mma16832(int c[4], const uint32_t a[4],
                                         const uint32_t b[2]) {
    asm volatile(
        "mma.sync.aligned.m16n8k32.row.col.s32.s8.s8.s32 "
        "{%0,%1,%2,%3}, {%4,%5,%6,%7}, {%8,%9}, {%0,%1,%2,%3};"
        : "+r"(c[0]), "+r"(c[1]), "+r"(c[2]), "+r"(c[3])
        : "r"(a[0]), "r"(a[1]), "r"(a[2]), "r"(a[3]), "r"(b[0]), "r"(b[1]));
}

// ---------------------------------------------------------------------------
// quant_rows: fp32 [rows][2048] -> int8 hi/lo + per-row scale q
//   x = q*(128*hi + lo/2), q = rowmax/16256
// ---------------------------------------------------------------------------
__global__ void quant_rows(const float* __restrict__ x,
                           signed char* __restrict__ h8,
                           signed char* __restrict__ l8,
                           float* __restrict__ qs)
{
    __shared__ float red[256];
    const int row = blockIdx.x;
    const int t = threadIdx.x;
    const float* xr = x + (size_t)row * EE;
    float m = 0.f;
    for (int i = t; i < EE / 4; i += 256) {
        float4 v = ((const float4*)xr)[i];
        m = fmaxf(m, fmaxf(fmaxf(fabsf(v.x), fabsf(v.y)),
                           fmaxf(fabsf(v.z), fabsf(v.w))));
    }
    red[t] = m;
    __syncthreads();
    for (int s = 128; s > 0; s >>= 1) {
        if (t < s) red[t] = fmaxf(red[t], red[t + s]);
        __syncthreads();
    }
    const float q = fmaxf(red[0], 1e-30f) * (1.0f / 16256.0f);
    if (t == 0) qs[row] = q;
    const float inv128q = 1.0f / (128.0f * q);
    const float q128 = 128.0f * q;
    const float twoinvq = 2.0f / q;
    for (int i = t; i < EE / 4; i += 256) {
        float4 v = ((const float4*)xr)[i];
        float vv[4] = {v.x, v.y, v.z, v.w};
        signed char hh[4], ll[4];
#pragma unroll
        for (int j = 0; j < 4; j++) {
            int ah = __float2int_rn(vv[j] * inv128q);
            ah = max(-127, min(127, ah));
            float r = vv[j] - q128 * (float)ah;
            int al = __float2int_rn(r * twoinvq);
            al = max(-128, min(127, al));
            hh[j] = (signed char)ah;
            ll[j] = (signed char)al;
        }
        ((char4*)h8)[(size_t)row * (EE / 4) + i] = make_char4(hh[0], hh[1], hh[2], hh[3]);
        ((char4*)l8)[(size_t)row * (EE / 4) + i] = make_char4(ll[0], ll[1], ll[2], ll[3]);
    }
}

// ---------------------------------------------------------------------------
// wquant4: W[K=2048][N] fp32 -> [N][K] int8 hi/lo + per-col scale.
// grid (64, 4): z selects weight; block (32,8); 32 cols per block.
// ---------------------------------------------------------------------------
__global__ void wquant4(
    const float* __restrict__ W0, signed char* __restrict__ h0, signed char* __restrict__ l0, float* __restrict__ s0,
    const float* __restrict__ W1, signed char* __restrict__ h1, signed char* __restrict__ l1, float* __restrict__ s1,
    const float* __restrict__ W2, signed char* __restrict__ h2, signed char* __restrict__ l2, float* __restrict__ s2,
    const float* __restrict__ W3, signed char* __restrict__ h3, signed char* __restrict__ l3, float* __restrict__ s3)
{
    const float* W; signed char *H8, *L8; float* S; int N;
    switch (blockIdx.y) {
        case 0: W = W0; H8 = h0; L8 = l0; S = s0; N = HQ*DD;  break;
        case 1: W = W1; H8 = h1; L8 = l1; S = s1; N = HKV*DD; break;
        case 2: W = W2; H8 = h2; L8 = l2; S = s2; N = HKV*DD; break;
        default:W = W3; H8 = h3; L8 = l3; S = s3; N = EE;     break;
    }
    const int n0 = blockIdx.x * 32;
    if (n0 >= N) return;
    const int K = EE;   // all weights have K = 2048 here

    __shared__ float pm[8][32];
    __shared__ float cq[32];
    __shared__ signed char th[32][36], tl[32][36];
    const int tx = threadIdx.x, ty = threadIdx.y;

    float m = 0.f;
    for (int k = ty; k < K; k += 8)
        m = fmaxf(m, fabsf(W[(size_t)k * N + n0 + tx]));
    pm[ty][tx] = m;
    __syncthreads();
    if (ty == 0) {
        float mm = pm[0][tx];
#pragma unroll
        for (int j = 1; j < 8; j++) mm = fmaxf(mm, pm[j][tx]);
        float q = fmaxf(mm, 1e-30f) * (1.0f / 16256.0f);
        cq[tx] = q;
        S[n0 + tx] = q;
    }
    __syncthreads();

    for (int k0 = 0; k0 < K; k0 += 32) {
        for (int i = ty; i < 32; i += 8) {
            float v = W[(size_t)(k0 + i) * N + n0 + tx];
            float q = cq[tx];
            int ah = __float2int_rn(v / (128.0f * q));
            ah = max(-127, min(127, ah));
            float r = v - 128.0f * q * (float)ah;
            int al = __float2int_rn(r * (2.0f / q));
            al = max(-128, min(127, al));
            th[tx][i] = (signed char)ah;
            tl[tx][i] = (signed char)al;
        }
        __syncthreads();
        for (int r = ty; r < 32; r += 8) {
            H8[(size_t)(n0 + r) * K + k0 + tx] = th[r][tx];
            L8[(size_t)(n0 + r) * K + k0 + tx] = tl[r][tx];
        }
        __syncthreads();
    }
}

// ---------------------------------------------------------------------------
// int8x3 GEMM core: 128x128 CTA tile, 512 threads (4x4 warps, 32x32 warp tile),
// BK=64 int8, double-buffered cp.async.
//   y = qx[row]*qw[col]*(16384*S_hh + 64*S_cross) + bias
// ---------------------------------------------------------------------------
#define BKI 64
#define SROWI 80
#define TBI (128 * SROWI)          // 10240
#define BUFI (4 * TBI)             // 40960
#define GSMEM_I8 (2 * BUFI)        // 81920

__device__ __forceinline__ void tile_cp8(uint32_t sdst,
                                         const signed char* __restrict__ g,
                                         int row0, int k0, int t)
{
    const signed char* gb = g + (size_t)row0 * EE + k0;
    const int r = t >> 2, c = (t & 3) << 4;
    cpa16(sdst + r * SROWI + c, gb + (size_t)r * EE + c);
}

struct I8Acc { int a1[2][4][4]; int a2[2][4][4]; };

__device__ __forceinline__ void gemm_core_i8(
    const signed char* __restrict__ Ah8, const signed char* __restrict__ Al8,
    const signed char* __restrict__ Bh8, const signed char* __restrict__ Bl8,
    uint32_t sbase, int t, int bm, int bn, I8Acc& acc)
{
    const int lane = t & 31, wid = t >> 5;
    const int wm = wid & 3, wn = wid >> 2;

    // prologue: chunk 0 -> buffer 0
    tile_cp8(sbase,           Ah8, bm, 0, t);
    tile_cp8(sbase + TBI,     Al8, bm, 0, t);
    tile_cp8(sbase + 2 * TBI, Bh8, bn, 0, t);
    tile_cp8(sbase + 3 * TBI, Bl8, bn, 0, t);
    CP_COMMIT();

    const int q = lane >> 3, r8 = lane & 7;
    const int arow = wm * 32 + (q & 1) * 8 + r8;
    const int acolb = (q >> 1) * 16;
    const int t16 = lane & 15;
    const int b4row = wn * 32 + (t16 & 7) + (lane >> 4) * 8;
    const int b4colb = (t16 >> 3) * 16;

    for (int kt = 0; kt < 32; kt++) {
        const uint32_t sb = sbase + (kt & 1) * BUFI;
        if (kt + 1 < 32) {
            const uint32_t sn = sbase + ((kt + 1) & 1) * BUFI;
            const int k0 = (kt + 1) * BKI;
            tile_cp8(sn,           Ah8, bm, k0, t);
            tile_cp8(sn + TBI,     Al8, bm, k0, t);
            tile_cp8(sn + 2 * TBI, Bh8, bn, k0, t);
            tile_cp8(sn + 3 * TBI, Bl8, bn, k0, t);
            CP_COMMIT();
            CP_WAIT(1);
        } else {
            CP_WAIT(0);
        }
        __syncthreads();

#pragma unroll
        for (int kk = 0; kk < 2; kk++) {
            const uint32_t abase = sb + arow * SROWI + kk * 32 + acolb;
            const uint32_t bbase = sb + 2 * TBI + b4row * SROWI + kk * 32 + b4colb;
            uint32_t ah_[2][4], al_[2][4], bh_[4][2], bl_[4][2];
#pragma unroll
            for (int mt = 0; mt < 2; mt++) {
                ldmx4(abase + mt * 16 * SROWI, ah_[mt]);
                ldmx4(abase + TBI + mt * 16 * SROWI, al_[mt]);
            }
#pragma unroll
            for (int ntp = 0; ntp < 2; ntp++) {
                uint32_t r4[4];
                ldmx4(bbase + ntp * 16 * SROWI, r4);
                bh_[2*ntp][0] = r4[0]; bh_[2*ntp][1] = r4[1];
                bh_[2*ntp+1][0] = r4[2]; bh_[2*ntp+1][1] = r4[3];
                ldmx4(bbase + TBI + ntp * 16 * SROWI, r4);
                bl_[2*ntp][0] = r4[0]; bl_[2*ntp][1] = r4[1];
                bl_[2*ntp+1][0] = r4[2]; bl_[2*ntp+1][1] = r4[3];
            }
#pragma unroll
            for (int mt = 0; mt < 2; mt++)
#pragma unroll
                for (int nt = 0; nt < 4; nt++) {
                    mma16832(acc.a1[mt][nt], ah_[mt], bh_[nt]);
                    mma16832(acc.a2[mt][nt], ah_[mt], bl_[nt]);
                    mma16832(acc.a2[mt][nt], al_[mt], bh_[nt]);
                }
        }
        __syncthreads();
    }
}

// Fused QKV projection (int8x3). 640 CTAs:
//   [0,512) Q (fp32 out), [512,576) K (fp32 out), [576,640) V (bf16 split out)
__global__ __launch_bounds__(512, 1)
void gemm_qkv_i8(const signed char* __restrict__ Xh, const signed char* __restrict__ Xl,
                 const float* __restrict__ qx,
                 const signed char* __restrict__ WQh, const signed char* __restrict__ WQl,
                 const float* __restrict__ qwQ, const float* __restrict__ bQ, float* __restrict__ CQ,
                 const signed char* __restrict__ WKh, const signed char* __restrict__ WKl,
                 const float* __restrict__ qwK, const float* __restrict__ bK, float* __restrict__ CK,
                 const signed char* __restrict__ WVh, const signed char* __restrict__ WVl,
                 const float* __restrict__ qwV, const float* __restrict__ bV,
                 __nv_bfloat16* __restrict__ VH, __nv_bfloat16* __restrict__ VL)
{
    extern __shared__ char sm[];
    const uint32_t sbase = smem_u32(sm);
    const int t = threadIdx.x;
    const int wid = t >> 5, lane = t & 31;
    const int wm = wid & 3, wn = wid >> 2;
    const int bid = blockIdx.x;

    const signed char *Bh, *Bl;
    const float *qw, *bias;
    float* Cout = nullptr;
    int bm, bn, N, mode;
    if (bid < 512) {
        Bh = WQh; Bl = WQl; qw = qwQ; bias = bQ; Cout = CQ;
        bn = (bid & 15) * 128; bm = (bid >> 4) * 128;
        N = HQ * DD; mode = 0;
    } else if (bid < 576) {
        int idx = bid - 512;
        Bh = WKh; Bl = WKl; qw = qwK; bias = bK; Cout = CK;
        bn = (idx & 1) * 128; bm = (idx >> 1) * 128;
        N = HKV * DD; mode = 0;
    } else {
        int idx = bid - 576;
        Bh = WVh; Bl = WVl; qw = qwV; bias = bV;
        bn = (idx & 1) * 128; bm = (idx >> 1) * 128;
        N = HKV * DD; mode = 1;
    }

    I8Acc acc;
#pragma unroll
    for (int mt = 0; mt < 2; mt++)
#pragma unroll
        for (int nt = 0; nt < 4; nt++)
#pragma unroll
            for (int e = 0; e < 4; e++) { acc.a1[mt][nt][e] = 0; acc.a2[mt][nt][e] = 0; }

    gemm_core_i8(Xh, Xl, Bh, Bl, sbase, t, bm, bn, acc);

    const int gid = lane >> 2, tid2 = (lane & 3) * 2;
#pragma unroll
    for (int mt = 0; mt < 2; mt++) {
        const int row = bm + wm * 32 + mt * 16 + gid;
        const float qx0 = qx[row], qx1 = qx[row + 8];
#pragma unroll
        for (int nt = 0; nt < 4; nt++) {
            const int col = bn + wn * 32 + nt * 8 + tid2;
            const float w0 = qw[col], w1 = qw[col + 1];
            const float b0 = bias[col], b1 = bias[col + 1];
            float v0 = qx0 * w0 * ((float)acc.a1[mt][nt][0] * 16384.f + (float)acc.a2[mt][nt][0] * 64.f) + b0;
            float v1 = qx0 * w1 * ((float)acc.a1[mt][nt][1] * 16384.f + (float)acc.a2[mt][nt][1] * 64.f) + b1;
            float v2 = qx1 * w0 * ((float)acc.a1[mt][nt][2] * 16384.f + (float)acc.a2[mt][nt][2] * 64.f) + b0;
            float v3 = qx1 * w1 * ((float)acc.a1[mt][nt][3] * 16384.f + (float)acc.a2[mt][nt][3] * 64.f) + b1;
            if (mode == 0) {
                *(float2*)&Cout[(size_t)row * N + col] = make_float2(v0, v1);
                *(float2*)&Cout[(size_t)(row + 8) * N + col] = make_float2(v2, v3);
            } else {
                __nv_bfloat162 h0 = __floats2bfloat162_rn(v0, v1);
                __nv_bfloat162 lo0 = __floats2bfloat162_rn(
                    v0 - __bfloat162float(h0.x), v1 - __bfloat162float(h0.y));
                __nv_bfloat162 h1 = __floats2bfloat162_rn(v2, v3);
                __nv_bfloat162 lo1 = __floats2bfloat162_rn(
                    v2 - __bfloat162float(h1.x), v3 - __bfloat162float(h1.y));
                *(__nv_bfloat162*)&VH[(size_t)row * N + col] = h0;
                *(__nv_bfloat162*)&VL[(size_t)row * N + col] = lo0;
                *(__nv_bfloat162*)&VH[(size_t)(row + 8) * N + col] = h1;
                *(__nv_bfloat162*)&VL[(size_t)(row + 8) * N + col] = lo1;
            }
        }
    }
}

// O projection (int8x3, fp32 out, no bias)
__global__ __launch_bounds__(512, 1)
void gemm_o_i8(const signed char* __restrict__ Ah8, const signed char* __restrict__ Al8,
               const float* __restrict__ qx,
               const signed char* __restrict__ Bh8, const signed char* __restrict__ Bl8,
               const float* __restrict__ qw, float* __restrict__ C)
{
    extern __shared__ char sm[];
    const uint32_t sbase = smem_u32(sm);
    const int t = threadIdx.x;
    const int wid = t >> 5, lane = t & 31;
    const int wm = wid & 3, wn = wid >> 2;
    const int bm = blockIdx.y * 128, bn = blockIdx.x * 128;

    I8Acc acc;
#pragma unroll
    for (int mt = 0; mt < 2; mt++)
#pragma unroll
        for (int nt = 0; nt < 4; nt++)
#pragma unroll
            for (int e = 0; e < 4; e++) { acc.a1[mt][nt][e] = 0; acc.a2[mt][nt][e] = 0; }

    gemm_core_i8(Ah8, Al8, Bh8, Bl8, sbase, t, bm, bn, acc);

    const int gid = lane >> 2, tid2 = (lane & 3) * 2;
#pragma unroll
    for (int mt = 0; mt < 2; mt++) {
        const int row = bm + wm * 32 + mt * 16 + gid;
        const float qx0 = qx[row], qx1 = qx[row + 8];
#pragma unroll
        for (int nt = 0; nt < 4; nt++) {
            const int col = bn + wn * 32 + nt * 8 + tid2;
            const float w0 = qw[col], w1 = qw[col + 1];
            float v0 = qx0 * w0 * ((float)acc.a1[mt][nt][0] * 16384.f + (float)acc.a2[mt][nt][0] * 64.f);
            float v1 = qx0 * w1 * ((float)acc.a1[mt][nt][1] * 16384.f + (float)acc.a2[mt][nt][1] * 64.f);
            float v2 = qx1 * w0 * ((float)acc.a1[mt][nt][2] * 16384.f + (float)acc.a2[mt][nt][2] * 64.f);
            float v3 = qx1 * w1 * ((float)acc.a1[mt][nt][3] * 16384.f + (float)acc.a2[mt][nt][3] * 64.f);
            *(float2*)&C[(size_t)row * EE + col] = make_float2(v0, v1);
            *(float2*)&C[(size_t)(row + 8) * EE + col] = make_float2(v2, v3);
        }
    }
}

// ---------------------------------------------------------------------------
// fused RoPE + bf16 split for Q and K: grid (MROWS, 2); z=0 Q, z=1 K
// ---------------------------------------------------------------------------
__global__ void rope_split2(const float* __restrict__ q,
                            __nv_bfloat16* __restrict__ qh,
                            __nv_bfloat16* __restrict__ ql,
                            const float* __restrict__ k,
                            __nv_bfloat16* __restrict__ kh,
                            __nv_bfloat16* __restrict__ kl, float qscale)
{
    __shared__ float cs[64], sn[64];
    const int row = blockIdx.x;
    const int z = blockIdx.y;
    const int pos = row & (LL - 1);
    const int t = threadIdx.x;
    if (t < 64) {
        float e   = (float)(2 * t) * (1.0f / (float)DD);
        float inv = powf(1000000.0f, -e);
        float ang = (float)pos * inv;
        cs[t] = cosf(ang);
        sn[t] = sinf(ang);
    }
    __syncthreads();
    const int H = z ? HKV : HQ;
    const float oscale = z ? 1.0f : qscale;
    const float* xr = (z ? k : q) + (size_t)row * H * DD;
    __nv_bfloat16* xh = z ? kh : qh;
    __nv_bfloat16* xl = z ? kl : ql;
    const size_t ob = (size_t)row * H * DD;
    for (int i = t; i < H * 64; i += blockDim.x) {
        int h = i >> 6;
        int d = i & 63;
        float x1 = xr[h * DD + d];
        float x2 = xr[h * DD + d + 64];
        float c = cs[d], s = sn[d];
        float y1 = (x1 * c - x2 * s) * oscale;
        float y2 = (x2 * c + x1 * s) * oscale;
        __nv_bfloat16 h1 = __float2bfloat16(y1);
        __nv_bfloat16 h2 = __float2bfloat16(y2);
        xh[ob + h * DD + d]      = h1;
        xh[ob + h * DD + d + 64] = h2;
        xl[ob + h * DD + d]      = __float2bfloat16(y1 - __bfloat162float(h1));
        xl[ob + h * DD + d + 64] = __float2bfloat16(y2 - __bfloat162float(h2));
    }
}

// ---------------------------------------------------------------------------
// Flash attention on tensor cores (mma.sync bf16x3), causal, GQA G=8.
// fp32 output (feeds int8 quant for O-proj).
// ---------------------------------------------------------------------------
#define KROW 272
#define ATILE (64 * KROW)
#define ABUF  (4 * ATILE)
#define ASMEM (2 * ABUF)

__global__ __launch_bounds__(256)
void attn_mma(const __nv_bfloat16* __restrict__ Qh,
              const __nv_bfloat16* __restrict__ Ql,
              const __nv_bfloat16* __restrict__ Kh,
              const __nv_bfloat16* __restrict__ Kl,
              const __nv_bfloat16* __restrict__ Vh,
              const __nv_bfloat16* __restrict__ Vl,
              float* __restrict__ o_out)
{
    extern __shared__ char sm[];
    const uint32_t sb = smem_u32(sm);
    const int t = threadIdx.x, w = t >> 5, lane = t & 31;
    const int qt = gridDim.x - 1 - blockIdx.x;
    const int bh = blockIdx.y;
    const int b = bh >> 4, h = bh & 15, hk = h >> 3;
    const int q0 = qt * 128;

    {
        const char* gqh = (const char*)(Qh + ((size_t)(b * LL + q0)) * (HQ * DD) + h * DD);
        const char* gql = (const char*)(Ql + ((size_t)(b * LL + q0)) * (HQ * DD) + h * DD);
#pragma unroll
        for (int i = 0; i < 8; i++) {
            int idx = t + i * 256;
            int r = idx >> 4;
            int c = (idx & 15) << 4;
            cpa16(sb + r * KROW + c,               gqh + (size_t)r * 4096 + c);
            cpa16(sb + 128 * KROW + r * KROW + c,  gql + (size_t)r * 4096 + c);
        }
        CP_COMMIT();
        CP_WAIT(0);
        __syncthreads();
    }

    uint32_t qfh[8][4], qfl[8][4];
    {
        const int qq = lane >> 3, r8 = lane & 7;
        const uint32_t qaddr = sb + (w * 16 + (qq & 1) * 8 + r8) * KROW + (qq >> 1) * 16;
#pragma unroll
        for (int c = 0; c < 8; c++) {
            ldmx4(qaddr + c * 32, qfh[c]);
            ldmx4(qaddr + 128 * KROW + c * 32, qfl[c]);
        }
    }
    __syncthreads();

    float oacc[16][4];
#pragma unroll
    for (int v = 0; v < 16; v++)
#pragma unroll
        for (int e = 0; e < 4; e++) oacc[v][e] = 0.f;
    float m0 = -1e30f, m1 = -1e30f, l0 = 0.f, l1 = 0.f;

    const int NT = 2 * qt + 2;
    const size_t kvrow = (size_t)(HKV * DD) * 2;

    {
        const size_t roff = ((size_t)(b * LL)) * (HKV * DD) + hk * DD;
        const char* srcs[4] = {(const char*)(Kh + roff), (const char*)(Kl + roff),
                               (const char*)(Vh + roff), (const char*)(Vl + roff)};
#pragma unroll
        for (int i = 0; i < 16; i++) {
            int idx = t + i * 256;
            int mat = idx >> 10;
            int r = (idx >> 4) & 63;
            int c = (idx & 15) << 4;
            cpa16(sb + mat * ATILE + r * KROW + c, srcs[mat] + (size_t)r * kvrow + c);
        }
        CP_COMMIT();
    }

    const int g = lane >> 2;
    const int row0 = q0 + w * 16 + g;
    const int colq = (lane & 3) * 2;

    for (int kt = 0; kt < NT; kt++) {
        if (kt + 1 < NT) {
            const uint32_t nb = sb + ((kt + 1) & 1) * ABUF;
            const size_t roff = ((size_t)(b * LL + (kt + 1) * 64)) * (HKV * DD) + hk * DD;
            const char* srcs[4] = {(const char*)(Kh + roff), (const char*)(Kl + roff),
                                   (const char*)(Vh + roff), (const char*)(Vl + roff)};
#pragma unroll
            for (int i = 0; i < 16; i++) {
                int idx = t + i * 256;
                int mat = idx >> 10;
                int r = (idx >> 4) & 63;
                int c = (idx & 15) << 4;
                cpa16(nb + mat * ATILE + r * KROW + c, srcs[mat] + (size_t)r * kvrow + c);
            }
            CP_COMMIT();
            CP_WAIT(1);
        } else {
            CP_WAIT(0);
        }
        __syncthreads();

        const uint32_t kb = sb + (kt & 1) * ABUF;
        const int kv0 = kt * 64;

        float s_[8][4];
#pragma unroll
        for (int j = 0; j < 8; j++)
#pragma unroll
            for (int e = 0; e < 4; e++) s_[j][e] = 0.f;

        const uint32_t kaddr = kb + (lane & 7) * KROW + (lane >> 3) * 16;
#pragma unroll
        for (int c32 = 0; c32 < 4; c32++) {
#pragma unroll
            for (int j = 0; j < 8; j++) {
                uint32_t kfh[4], kfl[4];
                ldmx4(kaddr + j * 8 * KROW + c32 * 64, kfh);
                ldmx4(kaddr + ATILE + j * 8 * KROW + c32 * 64, kfl);
                uint32_t bh0[2] = {kfh[0], kfh[1]}, bh1[2] = {kfh[2], kfh[3]};
                uint32_t bl0[2] = {kfl[0], kfl[1]}, bl1[2] = {kfl[2], kfl[3]};
                mma16816(s_[j], qfh[2 * c32],     bh0);
                mma16816(s_[j], qfh[2 * c32 + 1], bh1);
                mma16816(s_[j], qfh[2 * c32],     bl0);
                mma16816(s_[j], qfh[2 * c32 + 1], bl1);
                mma16816(s_[j], qfl[2 * c32],     bh0);
                mma16816(s_[j], qfl[2 * c32 + 1], bh1);
            }
        }

#pragma unroll
        for (int j = 0; j < 8; j++) {
            int c0 = kv0 + 8 * j + colq;
            if (c0 > row0)     s_[j][0] = -1e30f;
            if (c0 + 1 > row0) s_[j][1] = -1e30f;
            if (c0 > row0 + 8)     s_[j][2] = -1e30f;
            if (c0 + 1 > row0 + 8) s_[j][3] = -1e30f;
        }

        float mx0 = -1e30f, mx1 = -1e30f;
#pragma unroll
        for (int j = 0; j < 8; j++) {
            mx0 = fmaxf(mx0, fmaxf(s_[j][0], s_[j][1]));
            mx1 = fmaxf(mx1, fmaxf(s_[j][2], s_[j][3]));
        }
        mx0 = fmaxf(mx0, __shfl_xor_sync(0xffffffffu, mx0, 1));
        mx0 = fmaxf(mx0, __shfl_xor_sync(0xffffffffu, mx0, 2));
        mx1 = fmaxf(mx1, __shfl_xor_sync(0xffffffffu, mx1, 1));
        mx1 = fmaxf(mx1, __shfl_xor_sync(0xffffffffu, mx1, 2));
        const float m0n = fmaxf(m0, mx0), m1n = fmaxf(m1, mx1);
        const float cr0 = __expf(m0 - m0n), cr1 = __expf(m1 - m1n);
        float sum0 = 0.f, sum1 = 0.f;
#pragma unroll
        for (int j = 0; j < 8; j++) {
            s_[j][0] = __expf(s_[j][0] - m0n); sum0 += s_[j][0];
            s_[j][1] = __expf(s_[j][1] - m0n); sum0 += s_[j][1];
            s_[j][2] = __expf(s_[j][2] - m1n); sum1 += s_[j][2];
            s_[j][3] = __expf(s_[j][3] - m1n); sum1 += s_[j][3];
        }
        sum0 += __shfl_xor_sync(0xffffffffu, sum0, 1);
        sum0 += __shfl_xor_sync(0xffffffffu, sum0, 2);
        sum1 += __shfl_xor_sync(0xffffffffu, sum1, 1);
        sum1 += __shfl_xor_sync(0xffffffffu, sum1, 2);
        l0 = l0 * cr0 + sum0;  m0 = m0n;
        l1 = l1 * cr1 + sum1;  m1 = m1n;
#pragma unroll
        for (int v = 0; v < 16; v++) {
            oacc[v][0] *= cr0; oacc[v][1] *= cr0;
            oacc[v][2] *= cr1; oacc[v][3] *= cr1;
        }

        uint32_t ph01[8], ph23[8], pl01[8], pl23[8];
#pragma unroll
        for (int j = 0; j < 8; j++) {
            __nv_bfloat162 h01 = __floats2bfloat162_rn(s_[j][0], s_[j][1]);
            __nv_bfloat162 h23 = __floats2bfloat162_rn(s_[j][2], s_[j][3]);
            ph01[j] = *(uint32_t*)&h01;
            ph23[j] = *(uint32_t*)&h23;
            __nv_bfloat162 lo01 = __floats2bfloat162_rn(
                s_[j][0] - __bfloat162float(h01.x),
                s_[j][1] - __bfloat162float(h01.y));
            __nv_bfloat162 lo23 = __floats2bfloat162_rn(
                s_[j][2] - __bfloat162float(h23.x),
                s_[j][3] - __bfloat162float(h23.y));
            pl01[j] = *(uint32_t*)&lo01;
            pl23[j] = *(uint32_t*)&lo23;
        }

        const uint32_t vaddr = kb + 2 * ATILE + lane * KROW;
#pragma unroll
        for (int t32 = 0; t32 < 2; t32++) {
            uint32_t Ah0[4] = {ph01[4*t32],   ph23[4*t32],   ph01[4*t32+1], ph23[4*t32+1]};
            uint32_t Ah1[4] = {ph01[4*t32+2], ph23[4*t32+2], ph01[4*t32+3], ph23[4*t32+3]};
            uint32_t Al0[4] = {pl01[4*t32],   pl23[4*t32],   pl01[4*t32+1], pl23[4*t32+1]};
            uint32_t Al1[4] = {pl01[4*t32+2], pl23[4*t32+2], pl01[4*t32+3], pl23[4*t32+3]};
#pragma unroll
            for (int v = 0; v < 16; v++) {
                uint32_t vfh[4], vfl[4];
                ldmx4t(vaddr + t32 * 32 * KROW + v * 16, vfh);
                ldmx4t(vaddr + ATILE + t32 * 32 * KROW + v * 16, vfl);
                uint32_t bh0[2] = {vfh[0], vfh[1]}, bh1[2] = {vfh[2], vfh[3]};
                uint32_t bl0[2] = {vfl[0], vfl[1]}, bl1[2] = {vfl[2], vfl[3]};
                mma16816(oacc[v], Ah0, bh0);
                mma16816(oacc[v], Ah1, bh1);
                mma16816(oacc[v], Ah0, bl0);
                mma16816(oacc[v], Ah1, bl1);
                mma16816(oacc[v], Al0, bh0);
                mma16816(oacc[v], Al1, bh1);
            }
        }
        __syncthreads();
    }

    const float inv0 = 1.0f / l0, inv1 = 1.0f / l1;
    const size_t r0off = ((size_t)(b * LL + q0 + w * 16 + g)) * (HQ * DD) + h * DD + colq;
    const size_t r1off = r0off + 8 * (size_t)(HQ * DD);
#pragma unroll
    for (int v = 0; v < 16; v++) {
        *(float2*)&o_out[r0off + 8 * v] = make_float2(oacc[v][0] * inv0, oacc[v][1] * inv0);
        *(float2*)&o_out[r1off + 8 * v] = make_float2(oacc[v][2] * inv1, oacc[v][3] * inv1);
    }
}

// ---------------------------------------------------------------------------
// Launch
// ---------------------------------------------------------------------------
extern "C" void kernel_launch(void* const* d_in, const int* in_sizes, int n_in,
                              void* d_out, int out_size)
{
    const float* X  = (const float*)d_in[0];
    const float* Wq = (const float*)d_in[1];
    const float* bq = (const float*)d_in[2];
    const float* Wk = (const float*)d_in[3];
    const float* bk = (const float*)d_in[4];
    const float* Wv = (const float*)d_in[5];
    const float* bv = (const float*)d_in[6];
    const float* Wo = (const float*)d_in[7];
    float* out = (float*)d_out;

    float *qp, *kp, *xs;
    __nv_bfloat16 *ah, *al, *kh2, *kl2, *vh2, *vl2;
    signed char *x8h, *x8l, *wq8h, *wq8l, *wk8h, *wk8l, *wv8h, *wv8l, *wo8h, *wo8l;
    float *wqs, *wks, *wvs, *wos;
    cudaGetSymbolAddress((void**)&qp, g_q);
    cudaGetSymbolAddress((void**)&kp, g_k);
    cudaGetSymbolAddress((void**)&ah, g_ah);
    cudaGetSymbolAddress((void**)&al, g_al);
    cudaGetSymbolAddress((void**)&kh2, g_kh2);
    cudaGetSymbolAddress((void**)&kl2, g_kl2);
    cudaGetSymbolAddress((void**)&vh2, g_vh2);
    cudaGetSymbolAddress((void**)&vl2, g_vl2);
    cudaGetSymbolAddress((void**)&x8h, g_x8h);
    cudaGetSymbolAddress((void**)&x8l, g_x8l);
    cudaGetSymbolAddress((void**)&xs, g_xs);
    cudaGetSymbolAddress((void**)&wq8h, g_wq8h);
    cudaGetSymbolAddress((void**)&wq8l, g_wq8l);
    cudaGetSymbolAddress((void**)&wqs, g_wqs);
    cudaGetSymbolAddress((void**)&wk8h, g_wk8h);
    cudaGetSymbolAddress((void**)&wk8l, g_wk8l);
    cudaGetSymbolAddress((void**)&wks, g_wks);
    cudaGetSymbolAddress((void**)&wv8h, g_wv8h);
    cudaGetSymbolAddress((void**)&wv8l, g_wv8l);
    cudaGetSymbolAddress((void**)&wvs, g_wvs);
    cudaGetSymbolAddress((void**)&wo8h, g_wo8h);
    cudaGetSymbolAddress((void**)&wo8l, g_wo8l);
    cudaGetSymbolAddress((void**)&wos, g_wos);

    cudaFuncSetAttribute(gemm_qkv_i8,
                         cudaFuncAttributeMaxDynamicSharedMemorySize, GSMEM_I8);
    cudaFuncSetAttribute(gemm_o_i8,
                         cudaFuncAttributeMaxDynamicSharedMemorySize, GSMEM_I8);
    cudaFuncSetAttribute(attn_mma,
                         cudaFuncAttributeMaxDynamicSharedMemorySize, ASMEM);

    const float scale = 0.08838834764831845f;   // 1/sqrt(128)

    // Quantize X (per-row) + all weights (per-col, transposed)
    quant_rows<<<MROWS, 256>>>(X, x8h, x8l, xs);
    wquant4<<<dim3(64, 4), dim3(32, 8)>>>(
        Wq, wq8h, wq8l, wqs,
        Wk, wk8h, wk8l, wks,
        Wv, wv8h, wv8l, wvs,
        Wo, wo8h, wo8l, wos);

    // Fused Q+K+V projections (int8x3)
    gemm_qkv_i8<<<640, 512, GSMEM_I8>>>(
        x8h, x8l, xs,
        wq8h, wq8l, wqs, bq, qp,
        wk8h, wk8l, wks, bk, kp,
        wv8h, wv8l, wvs, bv, vh2, vl2);

    // RoPE + bf16 split for Q (scaled) and K
    rope_split2<<<dim3(MROWS, 2), 256>>>(qp, ah, al, kp, kh2, kl2, scale);

    // Attention (bf16x3) -> fp32 (reuses g_q)
    attn_mma<<<dim3(LL / 128, BB * HQ), 256, ASMEM>>>(
        ah, al, kh2, kl2, vh2, vl2, qp);

    // Quantize attention output, then O projection (int8x3)
    quant_rows<<<MROWS, 256>>>(qp, x8h, x8l, xs);
    gemm_o_i8<<<dim3(16, 32), 512, GSMEM_I8>>>(
        x8h, x8l, xs, wo8h, wo8l, wos, out);
}

// round 14
// speedup vs baseline: 2.2593x; 2.2593x over previous
#include <cuda_runtime.h>
#include <cuda_bf16.h>
#include <cstdint>
#include <cstddef>

// Problem constants
#define BB 2
#define LL 2048
#define EE 2048
#define HQ 16
#define HKV 2
#define DD 128
#define MROWS (BB*LL)   // 4096

// ---------------------------------------------------------------------------
// Scratch (device globals — no allocations allowed)
// ---------------------------------------------------------------------------
// bf16 split activations: X for gemms, then overwritten by rope'd Q
__device__ __nv_bfloat16 g_ah[(size_t)MROWS * EE];
__device__ __nv_bfloat16 g_al[(size_t)MROWS * EE];
// bf16 split K (post-rope) / V
__device__ __nv_bfloat16 g_kh2[(size_t)MROWS * HKV * DD];
__device__ __nv_bfloat16 g_kl2[(size_t)MROWS * HKV * DD];
__device__ __nv_bfloat16 g_vh2[(size_t)MROWS * HKV * DD];
__device__ __nv_bfloat16 g_vl2[(size_t)MROWS * HKV * DD];
// bf16 split attention output
__device__ __nv_bfloat16 g_oh[(size_t)MROWS * HQ * DD];
__device__ __nv_bfloat16 g_ol[(size_t)MROWS * HQ * DD];
// bf16 split transposed weights [N, K] (K-major)
__device__ __nv_bfloat16 g_wqh[(size_t)(HQ*DD) * EE];
__device__ __nv_bfloat16 g_wql[(size_t)(HQ*DD) * EE];
__device__ __nv_bfloat16 g_wkh[(size_t)(HKV*DD) * EE];
__device__ __nv_bfloat16 g_wkl[(size_t)(HKV*DD) * EE];
__device__ __nv_bfloat16 g_wvh[(size_t)(HKV*DD) * EE];
__device__ __nv_bfloat16 g_wvl[(size_t)(HKV*DD) * EE];
__device__ __nv_bfloat16 g_woh[(size_t)EE * (HQ*DD)];
__device__ __nv_bfloat16 g_wol[(size_t)EE * (HQ*DD)];

// ---------------------------------------------------------------------------
// PTX helpers (base-ISA: cp.async / ldmatrix / mma.sync)
// ---------------------------------------------------------------------------
__device__ __forceinline__ uint32_t smem_u32(const void* p) {
    uint32_t a;
    asm("{ .reg .u64 t; cvta.to.shared.u64 t, %1; cvt.u32.u64 %0, t; }"
        : "=r"(a) : "l"(p));
    return a;
}

__device__ __forceinline__ void cpa16(uint32_t d, const void* s) {
    asm volatile("cp.async.cg.shared.global [%0], [%1], 16;" :: "r"(d), "l"(s));
}
#define CP_COMMIT() asm volatile("cp.async.commit_group;")
#define CP_WAIT(n)  asm volatile("cp.async.wait_group %0;" :: "n"(n))

__device__ __forceinline__ void ldmx4(uint32_t a, uint32_t r[4]) {
    asm volatile("ldmatrix.sync.aligned.m8n8.x4.shared.b16 {%0,%1,%2,%3}, [%4];"
                 : "=r"(r[0]), "=r"(r[1]), "=r"(r[2]), "=r"(r[3]) : "r"(a));
}
__device__ __forceinline__ void ldmx4t(uint32_t a, uint32_t r[4]) {
    asm volatile("ldmatrix.sync.aligned.m8n8.x4.trans.shared.b16 {%0,%1,%2,%3}, [%4];"
                 : "=r"(r[0]), "=r"(r[1]), "=r"(r[2]), "=r"(r[3]) : "r"(a));
}

__device__ __forceinline__ void mma16816(float c[4], const uint32_t a[4],
                                         const uint32_t b[2]) {
    asm volatile(
        "mma.sync.aligned.m16n8k16.row.col.f32.bf16.bf16.f32 "
        "{%0,%1,%2,%3}, {%4,%5,%6,%7}, {%8,%9}, {%0,%1,%2,%3};"
        : "+f"(c[0]), "+f"(c[1]), "+f"(c[2]), "+f"(c[3])
        : "r"(a[0]), "r"(a[1]), "r"(a[2]), "r"(a[3]), "r"(b[0]), "r"(b[1]));
}

// ---------------------------------------------------------------------------
// split: fp32 -> bf16 hi + bf16 lo
// ---------------------------------------------------------------------------
__global__ void split_kernel(const float* __restrict__ x,
                             __nv_bfloat16* __restrict__ h,
                             __nv_bfloat16* __restrict__ l, int n4)
{
    int i = blockIdx.x * blockDim.x + threadIdx.x;
    if (i >= n4) return;
    float4 v = ((const float4*)x)[i];
    __nv_bfloat16 h0 = __float2bfloat16(v.x);
    __nv_bfloat16 h1 = __float2bfloat16(v.y);
    __nv_bfloat16 h2 = __float2bfloat16(v.z);
    __nv_bfloat16 h3 = __float2bfloat16(v.w);
    __nv_bfloat16 l0 = __float2bfloat16(v.x - __bfloat162float(h0));
    __nv_bfloat16 l1 = __float2bfloat16(v.y - __bfloat162float(h1));
    __nv_bfloat16 l2 = __float2bfloat16(v.z - __bfloat162float(h2));
    __nv_bfloat16 l3 = __float2bfloat16(v.w - __bfloat162float(h3));
    ((__nv_bfloat162*)h)[2*i]   = __halves2bfloat162(h0, h1);
    ((__nv_bfloat162*)h)[2*i+1] = __halves2bfloat162(h2, h3);
    ((__nv_bfloat162*)l)[2*i]   = __halves2bfloat162(l0, l1);
    ((__nv_bfloat162*)l)[2*i+1] = __halves2bfloat162(l2, l3);
}

// ---------------------------------------------------------------------------
// fused transpose+split of all 4 weights: W[K,N] fp32 -> Th,Tl [N,K] bf16
// ---------------------------------------------------------------------------
__global__ void tsplit4_kernel(
    const float* __restrict__ W0, __nv_bfloat16* __restrict__ h0, __nv_bfloat16* __restrict__ l0,
    const float* __restrict__ W1, __nv_bfloat16* __restrict__ h1, __nv_bfloat16* __restrict__ l1,
    const float* __restrict__ W2, __nv_bfloat16* __restrict__ h2, __nv_bfloat16* __restrict__ l2,
    const float* __restrict__ W3, __nv_bfloat16* __restrict__ h3, __nv_bfloat16* __restrict__ l3)
{
    const float* W; __nv_bfloat16 *Th, *Tl; int K, N;
    switch (blockIdx.z) {
        case 0: W = W0; Th = h0; Tl = l0; K = EE;    N = HQ*DD;  break;
        case 1: W = W1; Th = h1; Tl = l1; K = EE;    N = HKV*DD; break;
        case 2: W = W2; Th = h2; Tl = l2; K = EE;    N = HKV*DD; break;
        default:W = W3; Th = h3; Tl = l3; K = HQ*DD; N = EE;     break;
    }
    const int n0 = blockIdx.x * 32, k0 = blockIdx.y * 32;
    if (n0 >= N || k0 >= K) return;

    __shared__ float ts[32][33];
    const int tx = threadIdx.x, ty = threadIdx.y;
    for (int i = ty; i < 32; i += 8)
        ts[i][tx] = W[(size_t)(k0 + i) * N + n0 + tx];
    __syncthreads();
    for (int i = ty; i < 32; i += 8) {
        float v = ts[tx][i];
        __nv_bfloat16 hv = __float2bfloat16(v);
        __nv_bfloat16 lv = __float2bfloat16(v - __bfloat162float(hv));
        size_t o = (size_t)(n0 + i) * K + k0 + tx;
        Th[o] = hv;
        Tl[o] = lv;
    }
}

// ---------------------------------------------------------------------------
// bf16x3 GEMM core via mma.sync. 2 CTAs/SM.
// ---------------------------------------------------------------------------
#define BKG 32
#define SROW 80
#define TBYTES (128 * SROW)
#define BUFBYTES (4 * TBYTES)
#define GSMEM_BYTES (2 * BUFBYTES)   // 81920; epilogue reuses as 128x132 fp32

__device__ __forceinline__ void tile_cp(uint32_t sdst,
                                        const __nv_bfloat16* __restrict__ g,
                                        int ldk, int row0, int k0, int t)
{
    const char* gb = (const char*)(g + (size_t)row0 * ldk + k0);
    const size_t rs = (size_t)ldk * 2;
#pragma unroll
    for (int i = 0; i < 2; i++) {
        int idx = t + i * 256;
        int r = idx >> 2;
        int c = (idx & 3) << 4;
        cpa16(sdst + r * SROW + c, gb + (size_t)r * rs + c);
    }
}

__device__ __forceinline__ void gemm_core(
    const __nv_bfloat16* __restrict__ Ah, const __nv_bfloat16* __restrict__ Al,
    const __nv_bfloat16* __restrict__ Bh, const __nv_bfloat16* __restrict__ Bl,
    uint32_t sbase, int t, int bm, int bn, int K, float acc[4][4][4])
{
    const int lane = t & 31, wid = t >> 5;
    const int wm = wid & 1, wn = wid >> 1;
    const int NT = K / BKG;

    {
        tile_cp(sbase,              Ah, K, bm, 0, t);
        tile_cp(sbase + TBYTES,     Al, K, bm, 0, t);
        tile_cp(sbase + 2 * TBYTES, Bh, K, bn, 0, t);
        tile_cp(sbase + 3 * TBYTES, Bl, K, bn, 0, t);
        CP_COMMIT();
    }

    const int q = lane >> 3, r8 = lane & 7;
    const int arow = wm * 64 + (q & 1) * 8 + r8;
    const int acolb = ((q >> 1) * 8) * 2;
    const int t16 = lane & 15;
    const int b4row = wn * 32 + (t16 & 7) + ((lane >> 4) * 8);
    const int b4colb = (t16 >> 3) * 16;

    for (int kt = 0; kt < NT; kt++) {
        const uint32_t sb = sbase + (kt & 1) * BUFBYTES;
        if (kt + 1 < NT) {
            const uint32_t sn = sbase + ((kt + 1) & 1) * BUFBYTES;
            const int k0 = (kt + 1) * BKG;
            tile_cp(sn,              Ah, K, bm, k0, t);
            tile_cp(sn + TBYTES,     Al, K, bm, k0, t);
            tile_cp(sn + 2 * TBYTES, Bh, K, bn, k0, t);
            tile_cp(sn + 3 * TBYTES, Bl, K, bn, k0, t);
            CP_COMMIT();
            CP_WAIT(1);
        } else {
            CP_WAIT(0);
        }
        __syncthreads();

#pragma unroll
        for (int kk = 0; kk < 2; kk++) {
            const uint32_t abase = sb + arow * SROW + kk * 32 + acolb;
            const uint32_t bbase = sb + 2 * TBYTES + b4row * SROW + kk * 32 + b4colb;
            uint32_t ah_[4][4], al_[4][4], bh_[4][2], bl_[4][2];
#pragma unroll
            for (int mt = 0; mt < 4; mt++) {
                ldmx4(abase + mt * 16 * SROW, ah_[mt]);
                ldmx4(abase + TBYTES + mt * 16 * SROW, al_[mt]);
            }
#pragma unroll
            for (int ntp = 0; ntp < 2; ntp++) {
                uint32_t r4[4];
                ldmx4(bbase + ntp * 16 * SROW, r4);
                bh_[2*ntp][0] = r4[0]; bh_[2*ntp][1] = r4[1];
                bh_[2*ntp+1][0] = r4[2]; bh_[2*ntp+1][1] = r4[3];
                ldmx4(bbase + TBYTES + ntp * 16 * SROW, r4);
                bl_[2*ntp][0] = r4[0]; bl_[2*ntp][1] = r4[1];
                bl_[2*ntp+1][0] = r4[2]; bl_[2*ntp+1][1] = r4[3];
            }
#pragma unroll
            for (int mt = 0; mt < 4; mt++)
#pragma unroll
                for (int nt = 0; nt < 4; nt++) {
                    mma16816(acc[mt][nt], ah_[mt], bh_[nt]);
                    mma16816(acc[mt][nt], ah_[mt], bl_[nt]);
                    mma16816(acc[mt][nt], al_[mt], bh_[nt]);
                }
        }
        __syncthreads();
    }
}

// ---------------------------------------------------------------------------
// Fused QKV projection with RoPE in the epilogue. 1D grid of 640 CTAs:
//   [0,512)   Q tiles: bias + rope + 1/sqrt(D) scale -> split bf16
//   [512,576) K tiles: bias + rope                   -> split bf16
//   [576,640) V tiles: bias                          -> split bf16
// Each 128-col tile = exactly one head (d = local col), so the rope pair
// (d, d^64) is CTA-local: stage fp32 tile in smem, exchange, write.
// ---------------------------------------------------------------------------
__global__ __launch_bounds__(256, 2)
void gemm_qkv(const __nv_bfloat16* __restrict__ Ah,
              const __nv_bfloat16* __restrict__ Al,
              const __nv_bfloat16* __restrict__ BhQ, const __nv_bfloat16* __restrict__ BlQ,
              const float* __restrict__ bQ,
              __nv_bfloat16* __restrict__ QH, __nv_bfloat16* __restrict__ QL,
              const __nv_bfloat16* __restrict__ BhK, const __nv_bfloat16* __restrict__ BlK,
              const float* __restrict__ bK,
              __nv_bfloat16* __restrict__ KH, __nv_bfloat16* __restrict__ KL,
              const __nv_bfloat16* __restrict__ BhV, const __nv_bfloat16* __restrict__ BlV,
              const float* __restrict__ bV,
              __nv_bfloat16* __restrict__ VH, __nv_bfloat16* __restrict__ VL,
              float qscale)
{
    extern __shared__ char sm[];
    const uint32_t sbase = smem_u32(sm);
    const int t = threadIdx.x;
    const int wid = t >> 5, lane = t & 31;
    const int wm = wid & 1, wn = wid >> 1;
    const int bid = blockIdx.x;

    const __nv_bfloat16 *Bh, *Bl;
    const float* bias;
    __nv_bfloat16 *OH, *OL;
    int bm, bn, N;
    int rope;            // 1 = apply rope
    float oscale;
    if (bid < 512) {
        Bh = BhQ; Bl = BlQ; bias = bQ; OH = QH; OL = QL;
        bn = (bid & 15) * 128; bm = (bid >> 4) * 128;
        N = HQ * DD; rope = 1; oscale = qscale;
    } else if (bid < 576) {
        int idx = bid - 512;
        Bh = BhK; Bl = BlK; bias = bK; OH = KH; OL = KL;
        bn = (idx & 1) * 128; bm = (idx >> 1) * 128;
        N = HKV * DD; rope = 1; oscale = 1.0f;
    } else {
        int idx = bid - 576;
        Bh = BhV; Bl = BlV; bias = bV; OH = VH; OL = VL;
        bn = (idx & 1) * 128; bm = (idx >> 1) * 128;
        N = HKV * DD; rope = 0; oscale = 1.0f;
    }

    float acc[4][4][4];
#pragma unroll
    for (int mt = 0; mt < 4; mt++)
#pragma unroll
        for (int nt = 0; nt < 4; nt++)
#pragma unroll
            for (int i = 0; i < 4; i++) acc[mt][nt][i] = 0.f;

    gemm_core(Ah, Al, Bh, Bl, sbase, t, bm, bn, EE, acc);

    const int gid = lane >> 2, tid2 = (lane & 3) * 2;

    if (!rope) {
        // V: bias + split, direct
#pragma unroll
        for (int mt = 0; mt < 4; mt++) {
            const int row = bm + wm * 64 + mt * 16 + gid;
#pragma unroll
            for (int nt = 0; nt < 4; nt++) {
                const int col = bn + wn * 32 + nt * 8 + tid2;
                const float b0 = bias[col], b1 = bias[col + 1];
                float v0 = acc[mt][nt][0] + b0, v1 = acc[mt][nt][1] + b1;
                float v2 = acc[mt][nt][2] + b0, v3 = acc[mt][nt][3] + b1;
                __nv_bfloat162 h0 = __floats2bfloat162_rn(v0, v1);
                __nv_bfloat162 l0 = __floats2bfloat162_rn(
                    v0 - __bfloat162float(h0.x), v1 - __bfloat162float(h0.y));
                __nv_bfloat162 h1 = __floats2bfloat162_rn(v2, v3);
                __nv_bfloat162 l1 = __floats2bfloat162_rn(
                    v2 - __bfloat162float(h1.x), v3 - __bfloat162float(h1.y));
                *(__nv_bfloat162*)&OH[(size_t)row * N + col] = h0;
                *(__nv_bfloat162*)&OL[(size_t)row * N + col] = l0;
                *(__nv_bfloat162*)&OH[(size_t)(row + 8) * N + col] = h1;
                *(__nv_bfloat162*)&OL[(size_t)(row + 8) * N + col] = l1;
            }
        }
        return;
    }

    // Q/K: stage fp32 tile (bias added) in smem, then rope + split + store.
    float* sf = (float*)sm;   // [128][132]
#pragma unroll
    for (int mt = 0; mt < 4; mt++) {
        const int rl0 = wm * 64 + mt * 16 + gid;
#pragma unroll
        for (int nt = 0; nt < 4; nt++) {
            const int cl = wn * 32 + nt * 8 + tid2;
            const float b0 = bias[bn + cl], b1 = bias[bn + cl + 1];
            *(float2*)&sf[rl0 * 132 + cl] =
                make_float2(acc[mt][nt][0] + b0, acc[mt][nt][1] + b1);
            *(float2*)&sf[(rl0 + 8) * 132 + cl] =
                make_float2(acc[mt][nt][2] + b0, acc[mt][nt][3] + b1);
        }
    }
    __syncthreads();

    // inverse freqs for this thread's 8 column indices (i = col & 63)
    float invf[8];
#pragma unroll
    for (int nt = 0; nt < 4; nt++) {
        int c0 = (wn * 32 + nt * 8 + tid2) & 63;
        invf[2*nt]     = powf(1000000.0f, -(float)(2 * c0) * (1.0f / 128.0f));
        invf[2*nt + 1] = powf(1000000.0f, -(float)(2 * (c0 + 1)) * (1.0f / 128.0f));
    }

#pragma unroll
    for (int mt = 0; mt < 4; mt++) {
#pragma unroll
        for (int half = 0; half < 2; half++) {
            const int rl = wm * 64 + mt * 16 + gid + half * 8;
            const int rowg = bm + rl;
            const float pos = (float)(rowg & (LL - 1));
#pragma unroll
            for (int nt = 0; nt < 4; nt++) {
                const int cl = wn * 32 + nt * 8 + tid2;
                float2 v = *(float2*)&sf[rl * 132 + cl];
                float2 p = *(float2*)&sf[rl * 132 + (cl ^ 64)];
                float a0 = pos * invf[2*nt], a1 = pos * invf[2*nt + 1];
                float c0 = cosf(a0), s0 = sinf(a0);
                float c1 = cosf(a1), s1 = sinf(a1);
                float y0, y1;
                if (cl < 64) {
                    y0 = v.x * c0 - p.x * s0;
                    y1 = v.y * c1 - p.y * s1;
                } else {
                    y0 = v.x * c0 + p.x * s0;
                    y1 = v.y * c1 + p.y * s1;
                }
                y0 *= oscale; y1 *= oscale;
                __nv_bfloat162 h = __floats2bfloat162_rn(y0, y1);
                __nv_bfloat162 lo = __floats2bfloat162_rn(
                    y0 - __bfloat162float(h.x), y1 - __bfloat162float(h.y));
                *(__nv_bfloat162*)&OH[(size_t)rowg * N + bn + cl] = h;
                *(__nv_bfloat162*)&OL[(size_t)rowg * N + bn + cl] = lo;
            }
        }
    }
}

// O projection (fp32 out, no bias)
__global__ __launch_bounds__(256, 2)
void gemm_bf16x3(const __nv_bfloat16* __restrict__ Ah,
                 const __nv_bfloat16* __restrict__ Al,
                 const __nv_bfloat16* __restrict__ Bh,
                 const __nv_bfloat16* __restrict__ Bl,
                 float* __restrict__ C, int M, int N, int K)
{
    extern __shared__ char sm[];
    const uint32_t sbase = smem_u32(sm);
    const int t = threadIdx.x;
    const int wid = t >> 5, lane = t & 31;
    const int wm = wid & 1, wn = wid >> 1;
    const int bm = blockIdx.y * 128, bn = blockIdx.x * 128;

    float acc[4][4][4];
#pragma unroll
    for (int mt = 0; mt < 4; mt++)
#pragma unroll
        for (int nt = 0; nt < 4; nt++)
#pragma unroll
            for (int i = 0; i < 4; i++) acc[mt][nt][i] = 0.f;

    gemm_core(Ah, Al, Bh, Bl, sbase, t, bm, bn, K, acc);

    const int gid = lane >> 2, tid2 = (lane & 3) * 2;
#pragma unroll
    for (int mt = 0; mt < 4; mt++) {
        const int row = bm + wm * 64 + mt * 16 + gid;
#pragma unroll
        for (int nt = 0; nt < 4; nt++) {
            const int col = bn + wn * 32 + nt * 8 + tid2;
            *(float2*)&C[(size_t)row * N + col] =
                make_float2(acc[mt][nt][0], acc[mt][nt][1]);
            *(float2*)&C[(size_t)(row + 8) * N + col] =
                make_float2(acc[mt][nt][2], acc[mt][nt][3]);
        }
    }
}

// ---------------------------------------------------------------------------
// Flash attention on tensor cores (mma.sync bf16x3), causal, GQA G=8.
// 1D grid of 512 CTAs sorted heaviest-first: qt = 15-(bid>>5), bh = bid&31.
// ---------------------------------------------------------------------------
#define KROW 272
#define ATILE (64 * KROW)
#define ABUF  (4 * ATILE)
#define ASMEM (2 * ABUF)

__global__ __launch_bounds__(256)
void attn_mma(const __nv_bfloat16* __restrict__ Qh,
              const __nv_bfloat16* __restrict__ Ql,
              const __nv_bfloat16* __restrict__ Kh,
              const __nv_bfloat16* __restrict__ Kl,
              const __nv_bfloat16* __restrict__ Vh,
              const __nv_bfloat16* __restrict__ Vl,
              __nv_bfloat16* __restrict__ Oh,
              __nv_bfloat16* __restrict__ Ol)
{
    extern __shared__ char sm[];
    const uint32_t sb = smem_u32(sm);
    const int t = threadIdx.x, w = t >> 5, lane = t & 31;
    const int bid = blockIdx.x;
    const int qt = 15 - (bid >> 5);     // heaviest q-tiles first
    const int bh = bid & 31;
    const int b = bh >> 4, h = bh & 15, hk = h >> 3;
    const int q0 = qt * 128;

    {
        const char* gqh = (const char*)(Qh + ((size_t)(b * LL + q0)) * (HQ * DD) + h * DD);
        const char* gql = (const char*)(Ql + ((size_t)(b * LL + q0)) * (HQ * DD) + h * DD);
#pragma unroll
        for (int i = 0; i < 8; i++) {
            int idx = t + i * 256;
            int r = idx >> 4;
            int c = (idx & 15) << 4;
            cpa16(sb + r * KROW + c,               gqh + (size_t)r * 4096 + c);
            cpa16(sb + 128 * KROW + r * KROW + c,  gql + (size_t)r * 4096 + c);
        }
        CP_COMMIT();
        CP_WAIT(0);
        __syncthreads();
    }

    uint32_t qfh[8][4], qfl[8][4];
    {
        const int qq = lane >> 3, r8 = lane & 7;
        const uint32_t qaddr = sb + (w * 16 + (qq & 1) * 8 + r8) * KROW + (qq >> 1) * 16;
#pragma unroll
        for (int c = 0; c < 8; c++) {
            ldmx4(qaddr + c * 32, qfh[c]);
            ldmx4(qaddr + 128 * KROW + c * 32, qfl[c]);
        }
    }
    __syncthreads();

    float oacc[16][4];
#pragma unroll
    for (int v = 0; v < 16; v++)
#pragma unroll
        for (int e = 0; e < 4; e++) oacc[v][e] = 0.f;
    float m0 = -1e30f, m1 = -1e30f, l0 = 0.f, l1 = 0.f;

    const int NT = 2 * qt + 2;
    const size_t kvrow = (size_t)(HKV * DD) * 2;

    {
        const size_t roff = ((size_t)(b * LL)) * (HKV * DD) + hk * DD;
        const char* srcs[4] = {(const char*)(Kh + roff), (const char*)(Kl + roff),
                               (const char*)(Vh + roff), (const char*)(Vl + roff)};
#pragma unroll
        for (int i = 0; i < 16; i++) {
            int idx = t + i * 256;
            int mat = idx >> 10;
            int r = (idx >> 4) & 63;
            int c = (idx & 15) << 4;
            cpa16(sb + mat * ATILE + r * KROW + c, srcs[mat] + (size_t)r * kvrow + c);
        }
        CP_COMMIT();
    }

    const int g = lane >> 2;
    const int row0 = q0 + w * 16 + g;
    const int colq = (lane & 3) * 2;

    for (int kt = 0; kt < NT; kt++) {
        if (kt + 1 < NT) {
            const uint32_t nb = sb + ((kt + 1) & 1) * ABUF;
            const size_t roff = ((size_t)(b * LL + (kt + 1) * 64)) * (HKV * DD) + hk * DD;
            const char* srcs[4] = {(const char*)(Kh + roff), (const char*)(Kl + roff),
                                   (const char*)(Vh + roff), (const char*)(Vl + roff)};
#pragma unroll
            for (int i = 0; i < 16; i++) {
                int idx = t + i * 256;
                int mat = idx >> 10;
                int r = (idx >> 4) & 63;
                int c = (idx & 15) << 4;
                cpa16(nb + mat * ATILE + r * KROW + c, srcs[mat] + (size_t)r * kvrow + c);
            }
            CP_COMMIT();
            CP_WAIT(1);
        } else {
            CP_WAIT(0);
        }
        __syncthreads();

        const uint32_t kb = sb + (kt & 1) * ABUF;
        const int kv0 = kt * 64;

        float s_[8][4];
#pragma unroll
        for (int j = 0; j < 8; j++)
#pragma unroll
            for (int e = 0; e < 4; e++) s_[j][e] = 0.f;

        const uint32_t kaddr = kb + (lane & 7) * KROW + (lane >> 3) * 16;
#pragma unroll
        for (int c32 = 0; c32 < 4; c32++) {
#pragma unroll
            for (int j = 0; j < 8; j++) {
                uint32_t kfh[4], kfl[4];
                ldmx4(kaddr + j * 8 * KROW + c32 * 64, kfh);
                ldmx4(kaddr + ATILE + j * 8 * KROW + c32 * 64, kfl);
                uint32_t bh0[2] = {kfh[0], kfh[1]}, bh1[2] = {kfh[2], kfh[3]};
                uint32_t bl0[2] = {kfl[0], kfl[1]}, bl1[2] = {kfl[2], kfl[3]};
                mma16816(s_[j], qfh[2 * c32],     bh0);
                mma16816(s_[j], qfh[2 * c32 + 1], bh1);
                mma16816(s_[j], qfh[2 * c32],     bl0);
                mma16816(s_[j], qfh[2 * c32 + 1], bl1);
                mma16816(s_[j], qfl[2 * c32],     bh0);
                mma16816(s_[j], qfl[2 * c32 + 1], bh1);
            }
        }

#pragma unroll
        for (int j = 0; j < 8; j++) {
            int c0 = kv0 + 8 * j + colq;
            if (c0 > row0)     s_[j][0] = -1e30f;
            if (c0 + 1 > row0) s_[j][1] = -1e30f;
            if (c0 > row0 + 8)     s_[j][2] = -1e30f;
            if (c0 + 1 > row0 + 8) s_[j][3] = -1e30f;
        }

        float mx0 = -1e30f, mx1 = -1e30f;
#pragma unroll
        for (int j = 0; j < 8; j++) {
            mx0 = fmaxf(mx0, fmaxf(s_[j][0], s_[j][1]));
            mx1 = fmaxf(mx1, fmaxf(s_[j][2], s_[j][3]));
        }
        mx0 = fmaxf(mx0, __shfl_xor_sync(0xffffffffu, mx0, 1));
        mx0 = fmaxf(mx0, __shfl_xor_sync(0xffffffffu, mx0, 2));
        mx1 = fmaxf(mx1, __shfl_xor_sync(0xffffffffu, mx1, 1));
        mx1 = fmaxf(mx1, __shfl_xor_sync(0xffffffffu, mx1, 2));
        const float m0n = fmaxf(m0, mx0), m1n = fmaxf(m1, mx1);
        const float cr0 = __expf(m0 - m0n), cr1 = __expf(m1 - m1n);
        float sum0 = 0.f, sum1 = 0.f;
#pragma unroll
        for (int j = 0; j < 8; j++) {
            s_[j][0] = __expf(s_[j][0] - m0n); sum0 += s_[j][0];
            s_[j][1] = __expf(s_[j][1] - m0n); sum0 += s_[j][1];
            s_[j][2] = __expf(s_[j][2] - m1n); sum1 += s_[j][2];
            s_[j][3] = __expf(s_[j][3] - m1n); sum1 += s_[j][3];
        }
        sum0 += __shfl_xor_sync(0xffffffffu, sum0, 1);
        sum0 += __shfl_xor_sync(0xffffffffu, sum0, 2);
        sum1 += __shfl_xor_sync(0xffffffffu, sum1, 1);
        sum1 += __shfl_xor_sync(0xffffffffu, sum1, 2);
        l0 = l0 * cr0 + sum0;  m0 = m0n;
        l1 = l1 * cr1 + sum1;  m1 = m1n;
#pragma unroll
        for (int v = 0; v < 16; v++) {
            oacc[v][0] *= cr0; oacc[v][1] *= cr0;
            oacc[v][2] *= cr1; oacc[v][3] *= cr1;
        }

        uint32_t ph01[8], ph23[8], pl01[8], pl23[8];
#pragma unroll
        for (int j = 0; j < 8; j++) {
            __nv_bfloat162 h01 = __floats2bfloat162_rn(s_[j][0], s_[j][1]);
            __nv_bfloat162 h23 = __floats2bfloat162_rn(s_[j][2], s_[j][3]);
            ph01[j] = *(uint32_t*)&h01;
            ph23[j] = *(uint32_t*)&h23;
            __nv_bfloat162 lo01 = __floats2bfloat162_rn(
                s_[j][0] - __bfloat162float(h01.x),
                s_[j][1] - __bfloat162float(h01.y));
            __nv_bfloat162 lo23 = __floats2bfloat162_rn(
                s_[j][2] - __bfloat162float(h23.x),
                s_[j][3] - __bfloat162float(h23.y));
            pl01[j] = *(uint32_t*)&lo01;
            pl23[j] = *(uint32_t*)&lo23;
        }

        const uint32_t vaddr = kb + 2 * ATILE + lane * KROW;
#pragma unroll
        for (int t32 = 0; t32 < 2; t32++) {
            uint32_t Ah0[4] = {ph01[4*t32],   ph23[4*t32],   ph01[4*t32+1], ph23[4*t32+1]};
            uint32_t Ah1[4] = {ph01[4*t32+2], ph23[4*t32+2], ph01[4*t32+3], ph23[4*t32+3]};
            uint32_t Al0[4] = {pl01[4*t32],   pl23[4*t32],   pl01[4*t32+1], pl23[4*t32+1]};
            uint32_t Al1[4] = {pl01[4*t32+2], pl23[4*t32+2], pl01[4*t32+3], pl23[4*t32+3]};
#pragma unroll
            for (int v = 0; v < 16; v++) {
                uint32_t vfh[4], vfl[4];
                ldmx4t(vaddr + t32 * 32 * KROW + v * 16, vfh);
                ldmx4t(vaddr + ATILE + t32 * 32 * KROW + v * 16, vfl);
                uint32_t bh0[2] = {vfh[0], vfh[1]}, bh1[2] = {vfh[2], vfh[3]};
                uint32_t bl0[2] = {vfl[0], vfl[1]}, bl1[2] = {vfl[2], vfl[3]};
                mma16816(oacc[v], Ah0, bh0);
                mma16816(oacc[v], Ah1, bh1);
                mma16816(oacc[v], Ah0, bl0);
                mma16816(oacc[v], Ah1, bl1);
                mma16816(oacc[v], Al0, bh0);
                mma16816(oacc[v], Al1, bh1);
            }
        }
        __syncthreads();
    }

    const float inv0 = 1.0f / l0, inv1 = 1.0f / l1;
    const size_t r0off = ((size_t)(b * LL + q0 + w * 16 + g)) * (HQ * DD) + h * DD + colq;
    const size_t r1off = r0off + 8 * (size_t)(HQ * DD);
#pragma unroll
    for (int v = 0; v < 16; v++) {
        float a0 = oacc[v][0] * inv0, a1 = oacc[v][1] * inv0;
        float a2 = oacc[v][2] * inv1, a3 = oacc[v][3] * inv1;
        __nv_bfloat162 h0 = __floats2bfloat162_rn(a0, a1);
        __nv_bfloat162 lo0 = __floats2bfloat162_rn(
            a0 - __bfloat162float(h0.x), a1 - __bfloat162float(h0.y));
        __nv_bfloat162 h1 = __floats2bfloat162_rn(a2, a3);
        __nv_bfloat162 lo1 = __floats2bfloat162_rn(
            a2 - __bfloat162float(h1.x), a3 - __bfloat162float(h1.y));
        *(__nv_bfloat162*)&Oh[r0off + 8 * v] = h0;
        *(__nv_bfloat162*)&Ol[r0off + 8 * v] = lo0;
        *(__nv_bfloat162*)&Oh[r1off + 8 * v] = h1;
        *(__nv_bfloat162*)&Ol[r1off + 8 * v] = lo1;
    }
}

// ---------------------------------------------------------------------------
// Launch
// ---------------------------------------------------------------------------
extern "C" void kernel_launch(void* const* d_in, const int* in_sizes, int n_in,
                              void* d_out, int out_size)
{
    const float* X  = (const float*)d_in[0];
    const float* Wq = (const float*)d_in[1];
    const float* bq = (const float*)d_in[2];
    const float* Wk = (const float*)d_in[3];
    const float* bk = (const float*)d_in[4];
    const float* Wv = (const float*)d_in[5];
    const float* bv = (const float*)d_in[6];
    const float* Wo = (const float*)d_in[7];
    float* out = (float*)d_out;

    __nv_bfloat16 *ah, *al, *kh2, *kl2, *vh2, *vl2, *oh, *ol;
    __nv_bfloat16 *wqh, *wql, *wkh, *wkl, *wvh, *wvl, *woh, *wol;
    cudaGetSymbolAddress((void**)&ah, g_ah);
    cudaGetSymbolAddress((void**)&al, g_al);
    cudaGetSymbolAddress((void**)&kh2, g_kh2);
    cudaGetSymbolAddress((void**)&kl2, g_kl2);
    cudaGetSymbolAddress((void**)&vh2, g_vh2);
    cudaGetSymbolAddress((void**)&vl2, g_vl2);
    cudaGetSymbolAddress((void**)&oh, g_oh);
    cudaGetSymbolAddress((void**)&ol, g_ol);
    cudaGetSymbolAddress((void**)&wqh, g_wqh);
    cudaGetSymbolAddress((void**)&wql, g_wql);
    cudaGetSymbolAddress((void**)&wkh, g_wkh);
    cudaGetSymbolAddress((void**)&wkl, g_wkl);
    cudaGetSymbolAddress((void**)&wvh, g_wvh);
    cudaGetSymbolAddress((void**)&wvl, g_wvl);
    cudaGetSymbolAddress((void**)&woh, g_woh);
    cudaGetSymbolAddress((void**)&wol, g_wol);

    cudaFuncSetAttribute(gemm_qkv,
                         cudaFuncAttributeMaxDynamicSharedMemorySize, GSMEM_BYTES);
    cudaFuncSetAttribute(gemm_bf16x3,
                         cudaFuncAttributeMaxDynamicSharedMemorySize, GSMEM_BYTES);
    cudaFuncSetAttribute(attn_mma,
                         cudaFuncAttributeMaxDynamicSharedMemorySize, ASMEM);

    const int n4x = (int)((size_t)MROWS * EE / 4);
    const float scale = 0.08838834764831845f;   // 1/sqrt(128)

    // Split X + transpose/split all weights
    split_kernel<<<(n4x + 255) / 256, 256>>>(X, ah, al, n4x);
    tsplit4_kernel<<<dim3(64, 64, 4), dim3(32, 8)>>>(
        Wq, wqh, wql, Wk, wkh, wkl, Wv, wvh, wvl, Wo, woh, wol);

    // Fused Q+K+V projections with rope+split epilogue.
    // NOTE: Q output overwrites ah/al (the X splits) — safe because every CTA
    // finishes reading X (mainloop) before its epilogue writes, and Q tile
    // (rows bm.., head h) writes only columns this GEMM no longer reads.
    // To be strictly safe against cross-CTA races (another CTA still reading
    // X rows that this CTA overwrites), Q goes to oh/ol instead, which are
    // otherwise unused until attention output.
    gemm_qkv<<<640, 256, GSMEM_BYTES>>>(
        ah, al,
        wqh, wql, bq, oh, ol,          // Q -> oh/ol (free until attention)
        wkh, wkl, bk, kh2, kl2,
        wvh, wvl, bv, vh2, vl2,
        scale);

    // Attention: Q from oh/ol, output -> ah/al (X splits dead now)
    attn_mma<<<512, 256, ASMEM>>>(
        oh, ol, kh2, kl2, vh2, vl2, ah, al);

    // Output projection reads ah/al
    gemm_bf16x3<<<dim3(EE/128, MROWS/128), 256, GSMEM_BYTES>>>(
        ah, al, woh, wol, out, MROWS, EE, EE);
}

// round 15
// speedup vs baseline: 2.2949x; 1.0157x over previous
#include <cuda_runtime.h>
#include <cuda_bf16.h>
#include <cstdint>
#include <cstddef>

// Problem constants
#define BB 2
#define LL 2048
#define EE 2048
#define HQ 16
#define HKV 2
#define DD 128
#define MROWS (BB*LL)   // 4096

// ---------------------------------------------------------------------------
// Scratch (device globals — no allocations allowed)
// ---------------------------------------------------------------------------
__device__ __nv_bfloat16 g_ah[(size_t)MROWS * EE];
__device__ __nv_bfloat16 g_al[(size_t)MROWS * EE];
__device__ __nv_bfloat16 g_kh2[(size_t)MROWS * HKV * DD];
__device__ __nv_bfloat16 g_kl2[(size_t)MROWS * HKV * DD];
__device__ __nv_bfloat16 g_vh2[(size_t)MROWS * HKV * DD];
__device__ __nv_bfloat16 g_vl2[(size_t)MROWS * HKV * DD];
__device__ __nv_bfloat16 g_oh[(size_t)MROWS * HQ * DD];
__device__ __nv_bfloat16 g_ol[(size_t)MROWS * HQ * DD];
__device__ __nv_bfloat16 g_wqh[(size_t)(HQ*DD) * EE];
__device__ __nv_bfloat16 g_wql[(size_t)(HQ*DD) * EE];
__device__ __nv_bfloat16 g_wkh[(size_t)(HKV*DD) * EE];
__device__ __nv_bfloat16 g_wkl[(size_t)(HKV*DD) * EE];
__device__ __nv_bfloat16 g_wvh[(size_t)(HKV*DD) * EE];
__device__ __nv_bfloat16 g_wvl[(size_t)(HKV*DD) * EE];
__device__ __nv_bfloat16 g_woh[(size_t)EE * (HQ*DD)];
__device__ __nv_bfloat16 g_wol[(size_t)EE * (HQ*DD)];

// ---------------------------------------------------------------------------
// PTX helpers (base-ISA: cp.async / ldmatrix / mma.sync)
// ---------------------------------------------------------------------------
__device__ __forceinline__ uint32_t smem_u32(const void* p) {
    uint32_t a;
    asm("{ .reg .u64 t; cvta.to.shared.u64 t, %1; cvt.u32.u64 %0, t; }"
        : "=r"(a) : "l"(p));
    return a;
}

__device__ __forceinline__ void cpa16(uint32_t d, const void* s) {
    asm volatile("cp.async.cg.shared.global [%0], [%1], 16;" :: "r"(d), "l"(s));
}
#define CP_COMMIT() asm volatile("cp.async.commit_group;")
#define CP_WAIT(n)  asm volatile("cp.async.wait_group %0;" :: "n"(n))

__device__ __forceinline__ void ldmx4(uint32_t a, uint32_t r[4]) {
    asm volatile("ldmatrix.sync.aligned.m8n8.x4.shared.b16 {%0,%1,%2,%3}, [%4];"
                 : "=r"(r[0]), "=r"(r[1]), "=r"(r[2]), "=r"(r[3]) : "r"(a));
}
__device__ __forceinline__ void ldmx4t(uint32_t a, uint32_t r[4]) {
    asm volatile("ldmatrix.sync.aligned.m8n8.x4.trans.shared.b16 {%0,%1,%2,%3}, [%4];"
                 : "=r"(r[0]), "=r"(r[1]), "=r"(r[2]), "=r"(r[3]) : "r"(a));
}

__device__ __forceinline__ void mma16816(float c[4], const uint32_t a[4],
                                         const uint32_t b[2]) {
    asm volatile(
        "mma.sync.aligned.m16n8k16.row.col.f32.bf16.bf16.f32 "
        "{%0,%1,%2,%3}, {%4,%5,%6,%7}, {%8,%9}, {%0,%1,%2,%3};"
        : "+f"(c[0]), "+f"(c[1]), "+f"(c[2]), "+f"(c[3])
        : "r"(a[0]), "r"(a[1]), "r"(a[2]), "r"(a[3]), "r"(b[0]), "r"(b[1]));
}

// ---------------------------------------------------------------------------
// split: fp32 -> bf16 hi + bf16 lo
// ---------------------------------------------------------------------------
__global__ void split_kernel(const float* __restrict__ x,
                             __nv_bfloat16* __restrict__ h,
                             __nv_bfloat16* __restrict__ l, int n4)
{
    int i = blockIdx.x * blockDim.x + threadIdx.x;
    if (i >= n4) return;
    float4 v = ((const float4*)x)[i];
    __nv_bfloat16 h0 = __float2bfloat16(v.x);
    __nv_bfloat16 h1 = __float2bfloat16(v.y);
    __nv_bfloat16 h2 = __float2bfloat16(v.z);
    __nv_bfloat16 h3 = __float2bfloat16(v.w);
    __nv_bfloat16 l0 = __float2bfloat16(v.x - __bfloat162float(h0));
    __nv_bfloat16 l1 = __float2bfloat16(v.y - __bfloat162float(h1));
    __nv_bfloat16 l2 = __float2bfloat16(v.z - __bfloat162float(h2));
    __nv_bfloat16 l3 = __float2bfloat16(v.w - __bfloat162float(h3));
    ((__nv_bfloat162*)h)[2*i]   = __halves2bfloat162(h0, h1);
    ((__nv_bfloat162*)h)[2*i+1] = __halves2bfloat162(h2, h3);
    ((__nv_bfloat162*)l)[2*i]   = __halves2bfloat162(l0, l1);
    ((__nv_bfloat162*)l)[2*i+1] = __halves2bfloat162(l2, l3);
}

// ---------------------------------------------------------------------------
// fused transpose+split of all 4 weights: W[K,N] fp32 -> Th,Tl [N,K] bf16
// ---------------------------------------------------------------------------
__global__ void tsplit4_kernel(
    const float* __restrict__ W0, __nv_bfloat16* __restrict__ h0, __nv_bfloat16* __restrict__ l0,
    const float* __restrict__ W1, __nv_bfloat16* __restrict__ h1, __nv_bfloat16* __restrict__ l1,
    const float* __restrict__ W2, __nv_bfloat16* __restrict__ h2, __nv_bfloat16* __restrict__ l2,
    const float* __restrict__ W3, __nv_bfloat16* __restrict__ h3, __nv_bfloat16* __restrict__ l3)
{
    const float* W; __nv_bfloat16 *Th, *Tl; int K, N;
    switch (blockIdx.z) {
        case 0: W = W0; Th = h0; Tl = l0; K = EE;    N = HQ*DD;  break;
        case 1: W = W1; Th = h1; Tl = l1; K = EE;    N = HKV*DD; break;
        case 2: W = W2; Th = h2; Tl = l2; K = EE;    N = HKV*DD; break;
        default:W = W3; Th = h3; Tl = l3; K = HQ*DD; N = EE;     break;
    }
    const int n0 = blockIdx.x * 32, k0 = blockIdx.y * 32;
    if (n0 >= N || k0 >= K) return;

    __shared__ float ts[32][33];
    const int tx = threadIdx.x, ty = threadIdx.y;
    for (int i = ty; i < 32; i += 8)
        ts[i][tx] = W[(size_t)(k0 + i) * N + n0 + tx];
    __syncthreads();
    for (int i = ty; i < 32; i += 8) {
        float v = ts[tx][i];
        __nv_bfloat16 hv = __float2bfloat16(v);
        __nv_bfloat16 lv = __float2bfloat16(v - __bfloat162float(hv));
        size_t o = (size_t)(n0 + i) * K + k0 + tx;
        Th[o] = hv;
        Tl[o] = lv;
    }
}

// ---------------------------------------------------------------------------
// bf16x3 GEMM core via mma.sync. 2 CTAs/SM. Register-lean inner loop:
// B fragments resident per kk; A fragments streamed per mt (8 live).
// ---------------------------------------------------------------------------
#define BKG 32
#define SROW 80
#define TBYTES (128 * SROW)
#define BUFBYTES (4 * TBYTES)
#define GSMEM_BYTES (2 * BUFBYTES)   // 81920; epilogue reuses as 128x132 fp32

__device__ __forceinline__ void tile_cp(uint32_t sdst,
                                        const __nv_bfloat16* __restrict__ g,
                                        int ldk, int row0, int k0, int t)
{
    const char* gb = (const char*)(g + (size_t)row0 * ldk + k0);
    const size_t rs = (size_t)ldk * 2;
#pragma unroll
    for (int i = 0; i < 2; i++) {
        int idx = t + i * 256;
        int r = idx >> 2;
        int c = (idx & 3) << 4;
        cpa16(sdst + r * SROW + c, gb + (size_t)r * rs + c);
    }
}

__device__ __forceinline__ void gemm_core(
    const __nv_bfloat16* __restrict__ Ah, const __nv_bfloat16* __restrict__ Al,
    const __nv_bfloat16* __restrict__ Bh, const __nv_bfloat16* __restrict__ Bl,
    uint32_t sbase, int t, int bm, int bn, int K, float acc[4][4][4])
{
    const int lane = t & 31, wid = t >> 5;
    const int wm = wid & 1, wn = wid >> 1;
    const int NT = K / BKG;

    {
        tile_cp(sbase,              Ah, K, bm, 0, t);
        tile_cp(sbase + TBYTES,     Al, K, bm, 0, t);
        tile_cp(sbase + 2 * TBYTES, Bh, K, bn, 0, t);
        tile_cp(sbase + 3 * TBYTES, Bl, K, bn, 0, t);
        CP_COMMIT();
    }

    const int q = lane >> 3, r8 = lane & 7;
    const int arow = wm * 64 + (q & 1) * 8 + r8;
    const int acolb = ((q >> 1) * 8) * 2;
    const int t16 = lane & 15;
    const int b4row = wn * 32 + (t16 & 7) + ((lane >> 4) * 8);
    const int b4colb = (t16 >> 3) * 16;

    for (int kt = 0; kt < NT; kt++) {
        const uint32_t sb = sbase + (kt & 1) * BUFBYTES;
        if (kt + 1 < NT) {
            const uint32_t sn = sbase + ((kt + 1) & 1) * BUFBYTES;
            const int k0 = (kt + 1) * BKG;
            tile_cp(sn,              Ah, K, bm, k0, t);
            tile_cp(sn + TBYTES,     Al, K, bm, k0, t);
            tile_cp(sn + 2 * TBYTES, Bh, K, bn, k0, t);
            tile_cp(sn + 3 * TBYTES, Bl, K, bn, k0, t);
            CP_COMMIT();
            CP_WAIT(1);
        } else {
            CP_WAIT(0);
        }
        __syncthreads();

#pragma unroll
        for (int kk = 0; kk < 2; kk++) {
            const uint32_t abase = sb + arow * SROW + kk * 32 + acolb;
            const uint32_t bbase = sb + 2 * TBYTES + b4row * SROW + kk * 32 + b4colb;
            uint32_t bh_[4][2], bl_[4][2];
#pragma unroll
            for (int ntp = 0; ntp < 2; ntp++) {
                uint32_t r4[4];
                ldmx4(bbase + ntp * 16 * SROW, r4);
                bh_[2*ntp][0] = r4[0]; bh_[2*ntp][1] = r4[1];
                bh_[2*ntp+1][0] = r4[2]; bh_[2*ntp+1][1] = r4[3];
                ldmx4(bbase + TBYTES + ntp * 16 * SROW, r4);
                bl_[2*ntp][0] = r4[0]; bl_[2*ntp][1] = r4[1];
                bl_[2*ntp+1][0] = r4[2]; bl_[2*ntp+1][1] = r4[3];
            }
            // Stream A fragments: only 8 A-regs live at a time
#pragma unroll
            for (int mt = 0; mt < 4; mt++) {
                uint32_t ah_[4], al_[4];
                ldmx4(abase + mt * 16 * SROW, ah_);
                ldmx4(abase + TBYTES + mt * 16 * SROW, al_);
#pragma unroll
                for (int nt = 0; nt < 4; nt++) {
                    mma16816(acc[mt][nt], ah_, bh_[nt]);
                    mma16816(acc[mt][nt], ah_, bl_[nt]);
                    mma16816(acc[mt][nt], al_, bh_[nt]);
                }
            }
        }
        __syncthreads();
    }
}

// ---------------------------------------------------------------------------
// Fused QKV projection with RoPE in the epilogue. 1D grid of 640 CTAs.
// ---------------------------------------------------------------------------
__global__ __launch_bounds__(256, 2)
void gemm_qkv(const __nv_bfloat16* __restrict__ Ah,
              const __nv_bfloat16* __restrict__ Al,
              const __nv_bfloat16* __restrict__ BhQ, const __nv_bfloat16* __restrict__ BlQ,
              const float* __restrict__ bQ,
              __nv_bfloat16* __restrict__ QH, __nv_bfloat16* __restrict__ QL,
              const __nv_bfloat16* __restrict__ BhK, const __nv_bfloat16* __restrict__ BlK,
              const float* __restrict__ bK,
              __nv_bfloat16* __restrict__ KH, __nv_bfloat16* __restrict__ KL,
              const __nv_bfloat16* __restrict__ BhV, const __nv_bfloat16* __restrict__ BlV,
              const float* __restrict__ bV,
              __nv_bfloat16* __restrict__ VH, __nv_bfloat16* __restrict__ VL,
              float qscale)
{
    extern __shared__ char sm[];
    const uint32_t sbase = smem_u32(sm);
    const int t = threadIdx.x;
    const int wid = t >> 5, lane = t & 31;
    const int wm = wid & 1, wn = wid >> 1;
    const int bid = blockIdx.x;

    const __nv_bfloat16 *Bh, *Bl;
    const float* bias;
    __nv_bfloat16 *OH, *OL;
    int bm, bn, N;
    int rope;
    float oscale;
    if (bid < 512) {
        Bh = BhQ; Bl = BlQ; bias = bQ; OH = QH; OL = QL;
        bn = (bid & 15) * 128; bm = (bid >> 4) * 128;
        N = HQ * DD; rope = 1; oscale = qscale;
    } else if (bid < 576) {
        int idx = bid - 512;
        Bh = BhK; Bl = BlK; bias = bK; OH = KH; OL = KL;
        bn = (idx & 1) * 128; bm = (idx >> 1) * 128;
        N = HKV * DD; rope = 1; oscale = 1.0f;
    } else {
        int idx = bid - 576;
        Bh = BhV; Bl = BlV; bias = bV; OH = VH; OL = VL;
        bn = (idx & 1) * 128; bm = (idx >> 1) * 128;
        N = HKV * DD; rope = 0; oscale = 1.0f;
    }

    float acc[4][4][4];
#pragma unroll
    for (int mt = 0; mt < 4; mt++)
#pragma unroll
        for (int nt = 0; nt < 4; nt++)
#pragma unroll
            for (int i = 0; i < 4; i++) acc[mt][nt][i] = 0.f;

    gemm_core(Ah, Al, Bh, Bl, sbase, t, bm, bn, EE, acc);

    const int gid = lane >> 2, tid2 = (lane & 3) * 2;

    if (!rope) {
#pragma unroll
        for (int mt = 0; mt < 4; mt++) {
            const int row = bm + wm * 64 + mt * 16 + gid;
#pragma unroll
            for (int nt = 0; nt < 4; nt++) {
                const int col = bn + wn * 32 + nt * 8 + tid2;
                const float b0 = bias[col], b1 = bias[col + 1];
                float v0 = acc[mt][nt][0] + b0, v1 = acc[mt][nt][1] + b1;
                float v2 = acc[mt][nt][2] + b0, v3 = acc[mt][nt][3] + b1;
                __nv_bfloat162 h0 = __floats2bfloat162_rn(v0, v1);
                __nv_bfloat162 l0 = __floats2bfloat162_rn(
                    v0 - __bfloat162float(h0.x), v1 - __bfloat162float(h0.y));
                __nv_bfloat162 h1 = __floats2bfloat162_rn(v2, v3);
                __nv_bfloat162 l1 = __floats2bfloat162_rn(
                    v2 - __bfloat162float(h1.x), v3 - __bfloat162float(h1.y));
                *(__nv_bfloat162*)&OH[(size_t)row * N + col] = h0;
                *(__nv_bfloat162*)&OL[(size_t)row * N + col] = l0;
                *(__nv_bfloat162*)&OH[(size_t)(row + 8) * N + col] = h1;
                *(__nv_bfloat162*)&OL[(size_t)(row + 8) * N + col] = l1;
            }
        }
        return;
    }

    // Q/K: stage fp32 tile (bias added) in smem, then rope + split + store.
    float* sf = (float*)sm;   // [128][132]
#pragma unroll
    for (int mt = 0; mt < 4; mt++) {
        const int rl0 = wm * 64 + mt * 16 + gid;
#pragma unroll
        for (int nt = 0; nt < 4; nt++) {
            const int cl = wn * 32 + nt * 8 + tid2;
            const float b0 = bias[bn + cl], b1 = bias[bn + cl + 1];
            *(float2*)&sf[rl0 * 132 + cl] =
                make_float2(acc[mt][nt][0] + b0, acc[mt][nt][1] + b1);
            *(float2*)&sf[(rl0 + 8) * 132 + cl] =
                make_float2(acc[mt][nt][2] + b0, acc[mt][nt][3] + b1);
        }
    }
    __syncthreads();

    float invf[8];
#pragma unroll
    for (int nt = 0; nt < 4; nt++) {
        int c0 = (wn * 32 + nt * 8 + tid2) & 63;
        invf[2*nt]     = powf(1000000.0f, -(float)(2 * c0) * (1.0f / 128.0f));
        invf[2*nt + 1] = powf(1000000.0f, -(float)(2 * (c0 + 1)) * (1.0f / 128.0f));
    }

#pragma unroll
    for (int mt = 0; mt < 4; mt++) {
#pragma unroll
        for (int half = 0; half < 2; half++) {
            const int rl = wm * 64 + mt * 16 + gid + half * 8;
            const int rowg = bm + rl;
            const float pos = (float)(rowg & (LL - 1));
#pragma unroll
            for (int nt = 0; nt < 4; nt++) {
                const int cl = wn * 32 + nt * 8 + tid2;
                float2 v = *(float2*)&sf[rl * 132 + cl];
                float2 p = *(float2*)&sf[rl * 132 + (cl ^ 64)];
                float a0 = pos * invf[2*nt], a1 = pos * invf[2*nt + 1];
                float c0 = cosf(a0), s0 = sinf(a0);
                float c1 = cosf(a1), s1 = sinf(a1);
                float y0, y1;
                if (cl < 64) {
                    y0 = v.x * c0 - p.x * s0;
                    y1 = v.y * c1 - p.y * s1;
                } else {
                    y0 = v.x * c0 + p.x * s0;
                    y1 = v.y * c1 + p.y * s1;
                }
                y0 *= oscale; y1 *= oscale;
                __nv_bfloat162 h = __floats2bfloat162_rn(y0, y1);
                __nv_bfloat162 lo = __floats2bfloat162_rn(
                    y0 - __bfloat162float(h.x), y1 - __bfloat162float(h.y));
                *(__nv_bfloat162*)&OH[(size_t)rowg * N + bn + cl] = h;
                *(__nv_bfloat162*)&OL[(size_t)rowg * N + bn + cl] = lo;
            }
        }
    }
}

// O projection (fp32 out, no bias)
__global__ __launch_bounds__(256, 2)
void gemm_bf16x3(const __nv_bfloat16* __restrict__ Ah,
                 const __nv_bfloat16* __restrict__ Al,
                 const __nv_bfloat16* __restrict__ Bh,
                 const __nv_bfloat16* __restrict__ Bl,
                 float* __restrict__ C, int M, int N, int K)
{
    extern __shared__ char sm[];
    const uint32_t sbase = smem_u32(sm);
    const int t = threadIdx.x;
    const int wid = t >> 5, lane = t & 31;
    const int wm = wid & 1, wn = wid >> 1;
    const int bm = blockIdx.y * 128, bn = blockIdx.x * 128;

    float acc[4][4][4];
#pragma unroll
    for (int mt = 0; mt < 4; mt++)
#pragma unroll
        for (int nt = 0; nt < 4; nt++)
#pragma unroll
            for (int i = 0; i < 4; i++) acc[mt][nt][i] = 0.f;

    gemm_core(Ah, Al, Bh, Bl, sbase, t, bm, bn, K, acc);

    const int gid = lane >> 2, tid2 = (lane & 3) * 2;
#pragma unroll
    for (int mt = 0; mt < 4; mt++) {
        const int row = bm + wm * 64 + mt * 16 + gid;
#pragma unroll
        for (int nt = 0; nt < 4; nt++) {
            const int col = bn + wn * 32 + nt * 8 + tid2;
            *(float2*)&C[(size_t)row * N + col] =
                make_float2(acc[mt][nt][0], acc[mt][nt][1]);
            *(float2*)&C[(size_t)(row + 8) * N + col] =
                make_float2(acc[mt][nt][2], acc[mt][nt][3]);
        }
    }
}

// ---------------------------------------------------------------------------
// Flash attention on tensor cores (mma.sync bf16x3), causal, GQA G=8.
// 1D grid of 512 CTAs, heaviest q-tiles first.
// ---------------------------------------------------------------------------
#define KROW 272
#define ATILE (64 * KROW)
#define ABUF  (4 * ATILE)
#define ASMEM (2 * ABUF)

__global__ __launch_bounds__(256)
void attn_mma(const __nv_bfloat16* __restrict__ Qh,
              const __nv_bfloat16* __restrict__ Ql,
              const __nv_bfloat16* __restrict__ Kh,
              const __nv_bfloat16* __restrict__ Kl,
              const __nv_bfloat16* __restrict__ Vh,
              const __nv_bfloat16* __restrict__ Vl,
              __nv_bfloat16* __restrict__ Oh,
              __nv_bfloat16* __restrict__ Ol)
{
    extern __shared__ char sm[];
    const uint32_t sb = smem_u32(sm);
    const int t = threadIdx.x, w = t >> 5, lane = t & 31;
    const int bid = blockIdx.x;
    const int qt = 15 - (bid >> 5);
    const int bh = bid & 31;
    const int b = bh >> 4, h = bh & 15, hk = h >> 3;
    const int q0 = qt * 128;

    {
        const char* gqh = (const char*)(Qh + ((size_t)(b * LL + q0)) * (HQ * DD) + h * DD);
        const char* gql = (const char*)(Ql + ((size_t)(b * LL + q0)) * (HQ * DD) + h * DD);
#pragma unroll
        for (int i = 0; i < 8; i++) {
            int idx = t + i * 256;
            int r = idx >> 4;
            int c = (idx & 15) << 4;
            cpa16(sb + r * KROW + c,               gqh + (size_t)r * 4096 + c);
            cpa16(sb + 128 * KROW + r * KROW + c,  gql + (size_t)r * 4096 + c);
        }
        CP_COMMIT();
        CP_WAIT(0);
        __syncthreads();
    }

    uint32_t qfh[8][4], qfl[8][4];
    {
        const int qq = lane >> 3, r8 = lane & 7;
        const uint32_t qaddr = sb + (w * 16 + (qq & 1) * 8 + r8) * KROW + (qq >> 1) * 16;
#pragma unroll
        for (int c = 0; c < 8; c++) {
            ldmx4(qaddr + c * 32, qfh[c]);
            ldmx4(qaddr + 128 * KROW + c * 32, qfl[c]);
        }
    }
    __syncthreads();

    float oacc[16][4];
#pragma unroll
    for (int v = 0; v < 16; v++)
#pragma unroll
        for (int e = 0; e < 4; e++) oacc[v][e] = 0.f;
    float m0 = -1e30f, m1 = -1e30f, l0 = 0.f, l1 = 0.f;

    const int NT = 2 * qt + 2;
    const size_t kvrow = (size_t)(HKV * DD) * 2;

    {
        const size_t roff = ((size_t)(b * LL)) * (HKV * DD) + hk * DD;
        const char* srcs[4] = {(const char*)(Kh + roff), (const char*)(Kl + roff),
                               (const char*)(Vh + roff), (const char*)(Vl + roff)};
#pragma unroll
        for (int i = 0; i < 16; i++) {
            int idx = t + i * 256;
            int mat = idx >> 10;
            int r = (idx >> 4) & 63;
            int c = (idx & 15) << 4;
            cpa16(sb + mat * ATILE + r * KROW + c, srcs[mat] + (size_t)r * kvrow + c);
        }
        CP_COMMIT();
    }

    const int g = lane >> 2;
    const int row0 = q0 + w * 16 + g;
    const int colq = (lane & 3) * 2;

    for (int kt = 0; kt < NT; kt++) {
        if (kt + 1 < NT) {
            const uint32_t nb = sb + ((kt + 1) & 1) * ABUF;
            const size_t roff = ((size_t)(b * LL + (kt + 1) * 64)) * (HKV * DD) + hk * DD;
            const char* srcs[4] = {(const char*)(Kh + roff), (const char*)(Kl + roff),
                                   (const char*)(Vh + roff), (const char*)(Vl + roff)};
#pragma unroll
            for (int i = 0; i < 16; i++) {
                int idx = t + i * 256;
                int mat = idx >> 10;
                int r = (idx >> 4) & 63;
                int c = (idx & 15) << 4;
                cpa16(nb + mat * ATILE + r * KROW + c, srcs[mat] + (size_t)r * kvrow + c);
            }
            CP_COMMIT();
            CP_WAIT(1);
        } else {
            CP_WAIT(0);
        }
        __syncthreads();

        const uint32_t kb = sb + (kt & 1) * ABUF;
        const int kv0 = kt * 64;

        float s_[8][4];
#pragma unroll
        for (int j = 0; j < 8; j++)
#pragma unroll
            for (int e = 0; e < 4; e++) s_[j][e] = 0.f;

        const uint32_t kaddr = kb + (lane & 7) * KROW + (lane >> 3) * 16;
#pragma unroll
        for (int c32 = 0; c32 < 4; c32++) {
#pragma unroll
            for (int j = 0; j < 8; j++) {
                uint32_t kfh[4], kfl[4];
                ldmx4(kaddr + j * 8 * KROW + c32 * 64, kfh);
                ldmx4(kaddr + ATILE + j * 8 * KROW + c32 * 64, kfl);
                uint32_t bh0[2] = {kfh[0], kfh[1]}, bh1[2] = {kfh[2], kfh[3]};
                uint32_t bl0[2] = {kfl[0], kfl[1]}, bl1[2] = {kfl[2], kfl[3]};
                mma16816(s_[j], qfh[2 * c32],     bh0);
                mma16816(s_[j], qfh[2 * c32 + 1], bh1);
                mma16816(s_[j], qfh[2 * c32],     bl0);
                mma16816(s_[j], qfh[2 * c32 + 1], bl1);
                mma16816(s_[j], qfl[2 * c32],     bh0);
                mma16816(s_[j], qfl[2 * c32 + 1], bh1);
            }
        }

#pragma unroll
        for (int j = 0; j < 8; j++) {
            int c0 = kv0 + 8 * j + colq;
            if (c0 > row0)     s_[j][0] = -1e30f;
            if (c0 + 1 > row0) s_[j][1] = -1e30f;
            if (c0 > row0 + 8)     s_[j][2] = -1e30f;
            if (c0 + 1 > row0 + 8) s_[j][3] = -1e30f;
        }

        float mx0 = -1e30f, mx1 = -1e30f;
#pragma unroll
        for (int j = 0; j < 8; j++) {
            mx0 = fmaxf(mx0, fmaxf(s_[j][0], s_[j][1]));
            mx1 = fmaxf(mx1, fmaxf(s_[j][2], s_[j][3]));
        }
        mx0 = fmaxf(mx0, __shfl_xor_sync(0xffffffffu, mx0, 1));
        mx0 = fmaxf(mx0, __shfl_xor_sync(0xffffffffu, mx0, 2));
        mx1 = fmaxf(mx1, __shfl_xor_sync(0xffffffffu, mx1, 1));
        mx1 = fmaxf(mx1, __shfl_xor_sync(0xffffffffu, mx1, 2));
        const float m0n = fmaxf(m0, mx0), m1n = fmaxf(m1, mx1);
        const float cr0 = __expf(m0 - m0n), cr1 = __expf(m1 - m1n);
        float sum0 = 0.f, sum1 = 0.f;
#pragma unroll
        for (int j = 0; j < 8; j++) {
            s_[j][0] = __expf(s_[j][0] - m0n); sum0 += s_[j][0];
            s_[j][1] = __expf(s_[j][1] - m0n); sum0 += s_[j][1];
            s_[j][2] = __expf(s_[j][2] - m1n); sum1 += s_[j][2];
            s_[j][3] = __expf(s_[j][3] - m1n); sum1 += s_[j][3];
        }
        sum0 += __shfl_xor_sync(0xffffffffu, sum0, 1);
        sum0 += __shfl_xor_sync(0xffffffffu, sum0, 2);
        sum1 += __shfl_xor_sync(0xffffffffu, sum1, 1);
        sum1 += __shfl_xor_sync(0xffffffffu, sum1, 2);
        l0 = l0 * cr0 + sum0;  m0 = m0n;
        l1 = l1 * cr1 + sum1;  m1 = m1n;
#pragma unroll
        for (int v = 0; v < 16; v++) {
            oacc[v][0] *= cr0; oacc[v][1] *= cr0;
            oacc[v][2] *= cr1; oacc[v][3] *= cr1;
        }

        // ---- O += P V (bf16x3); P packed per-t32 (register-lean) ----
        const uint32_t vaddr = kb + 2 * ATILE + lane * KROW;
#pragma unroll
        for (int t32 = 0; t32 < 2; t32++) {
            uint32_t Ah0[4], Ah1[4], Al0[4], Al1[4];
#pragma unroll
            for (int u = 0; u < 4; u++) {
                const int j = 4 * t32 + u;
                __nv_bfloat162 h01 = __floats2bfloat162_rn(s_[j][0], s_[j][1]);
                __nv_bfloat162 h23 = __floats2bfloat162_rn(s_[j][2], s_[j][3]);
                __nv_bfloat162 lo01 = __floats2bfloat162_rn(
                    s_[j][0] - __bfloat162float(h01.x),
                    s_[j][1] - __bfloat162float(h01.y));
                __nv_bfloat162 lo23 = __floats2bfloat162_rn(
                    s_[j][2] - __bfloat162float(h23.x),
                    s_[j][3] - __bfloat162float(h23.y));
                uint32_t* Ahp = (u < 2) ? Ah0 : Ah1;
                uint32_t* Alp = (u < 2) ? Al0 : Al1;
                const int base = (u & 1) * 2;
                Ahp[base]     = *(uint32_t*)&h01;
                Ahp[base + 1] = *(uint32_t*)&h23;
                Alp[base]     = *(uint32_t*)&lo01;
                Alp[base + 1] = *(uint32_t*)&lo23;
            }
#pragma unroll
            for (int v = 0; v < 16; v++) {
                uint32_t vfh[4], vfl[4];
                ldmx4t(vaddr + t32 * 32 * KROW + v * 16, vfh);
                ldmx4t(vaddr + ATILE + t32 * 32 * KROW + v * 16, vfl);
                uint32_t bh0[2] = {vfh[0], vfh[1]}, bh1[2] = {vfh[2], vfh[3]};
                uint32_t bl0[2] = {vfl[0], vfl[1]}, bl1[2] = {vfl[2], vfl[3]};
                mma16816(oacc[v], Ah0, bh0);
                mma16816(oacc[v], Ah1, bh1);
                mma16816(oacc[v], Ah0, bl0);
                mma16816(oacc[v], Ah1, bl1);
                mma16816(oacc[v], Al0, bh0);
                mma16816(oacc[v], Al1, bh1);
            }
        }
        __syncthreads();
    }

    const float inv0 = 1.0f / l0, inv1 = 1.0f / l1;
    const size_t r0off = ((size_t)(b * LL + q0 + w * 16 + g)) * (HQ * DD) + h * DD + colq;
    const size_t r1off = r0off + 8 * (size_t)(HQ * DD);
#pragma unroll
    for (int v = 0; v < 16; v++) {
        float a0 = oacc[v][0] * inv0, a1 = oacc[v][1] * inv0;
        float a2 = oacc[v][2] * inv1, a3 = oacc[v][3] * inv1;
        __nv_bfloat162 h0 = __floats2bfloat162_rn(a0, a1);
        __nv_bfloat162 lo0 = __floats2bfloat162_rn(
            a0 - __bfloat162float(h0.x), a1 - __bfloat162float(h0.y));
        __nv_bfloat162 h1 = __floats2bfloat162_rn(a2, a3);
        __nv_bfloat162 lo1 = __floats2bfloat162_rn(
            a2 - __bfloat162float(h1.x), a3 - __bfloat162float(h1.y));
        *(__nv_bfloat162*)&Oh[r0off + 8 * v] = h0;
        *(__nv_bfloat162*)&Ol[r0off + 8 * v] = lo0;
        *(__nv_bfloat162*)&Oh[r1off + 8 * v] = h1;
        *(__nv_bfloat162*)&Ol[r1off + 8 * v] = lo1;
    }
}

// ---------------------------------------------------------------------------
// Launch
// ---------------------------------------------------------------------------
extern "C" void kernel_launch(void* const* d_in, const int* in_sizes, int n_in,
                              void* d_out, int out_size)
{
    const float* X  = (const float*)d_in[0];
    const float* Wq = (const float*)d_in[1];
    const float* bq = (const float*)d_in[2];
    const float* Wk = (const float*)d_in[3];
    const float* bk = (const float*)d_in[4];
    const float* Wv = (const float*)d_in[5];
    const float* bv = (const float*)d_in[6];
    const float* Wo = (const float*)d_in[7];
    float* out = (float*)d_out;

    __nv_bfloat16 *ah, *al, *kh2, *kl2, *vh2, *vl2, *oh, *ol;
    __nv_bfloat16 *wqh, *wql, *wkh, *wkl, *wvh, *wvl, *woh, *wol;
    cudaGetSymbolAddress((void**)&ah, g_ah);
    cudaGetSymbolAddress((void**)&al, g_al);
    cudaGetSymbolAddress((void**)&kh2, g_kh2);
    cudaGetSymbolAddress((void**)&kl2, g_kl2);
    cudaGetSymbolAddress((void**)&vh2, g_vh2);
    cudaGetSymbolAddress((void**)&vl2, g_vl2);
    cudaGetSymbolAddress((void**)&oh, g_oh);
    cudaGetSymbolAddress((void**)&ol, g_ol);
    cudaGetSymbolAddress((void**)&wqh, g_wqh);
    cudaGetSymbolAddress((void**)&wql, g_wql);
    cudaGetSymbolAddress((void**)&wkh, g_wkh);
    cudaGetSymbolAddress((void**)&wkl, g_wkl);
    cudaGetSymbolAddress((void**)&wvh, g_wvh);
    cudaGetSymbolAddress((void**)&wvl, g_wvl);
    cudaGetSymbolAddress((void**)&woh, g_woh);
    cudaGetSymbolAddress((void**)&wol, g_wol);

    cudaFuncSetAttribute(gemm_qkv,
                         cudaFuncAttributeMaxDynamicSharedMemorySize, GSMEM_BYTES);
    cudaFuncSetAttribute(gemm_bf16x3,
                         cudaFuncAttributeMaxDynamicSharedMemorySize, GSMEM_BYTES);
    cudaFuncSetAttribute(attn_mma,
                         cudaFuncAttributeMaxDynamicSharedMemorySize, ASMEM);

    const int n4x = (int)((size_t)MROWS * EE / 4);
    const float scale = 0.08838834764831845f;   // 1/sqrt(128)

    // Split X + transpose/split all weights
    split_kernel<<<(n4x + 255) / 256, 256>>>(X, ah, al, n4x);
    tsplit4_kernel<<<dim3(64, 64, 4), dim3(32, 8)>>>(
        Wq, wqh, wql, Wk, wkh, wkl, Wv, wvh, wvl, Wo, woh, wol);

    // Fused Q+K+V projections with rope+split epilogue (Q -> oh/ol)
    gemm_qkv<<<640, 256, GSMEM_BYTES>>>(
        ah, al,
        wqh, wql, bq, oh, ol,
        wkh, wkl, bk, kh2, kl2,
        wvh, wvl, bv, vh2, vl2,
        scale);

    // Attention: Q from oh/ol, output -> ah/al (X splits dead now)
    attn_mma<<<512, 256, ASMEM>>>(
        oh, ol, kh2, kl2, vh2, vl2, ah, al);

    // Output projection reads ah/al
    gemm_bf16x3<<<dim3(EE/128, MROWS/128), 256, GSMEM_BYTES>>>(
        ah, al, woh, wol, out, MROWS, EE, EE);
}

// round 16
// speedup vs baseline: 2.3375x; 1.0186x over previous
#include <cuda_runtime.h>
#include <cuda_bf16.h>
#include <cstdint>
#include <cstddef>

// Problem constants
#define BB 2
#define LL 2048
#define EE 2048
#define HQ 16
#define HKV 2
#define DD 128
#define MROWS (BB*LL)   // 4096

// ---------------------------------------------------------------------------
// Scratch (device globals — no allocations allowed)
// ---------------------------------------------------------------------------
__device__ __nv_bfloat16 g_ah[(size_t)MROWS * EE];
__device__ __nv_bfloat16 g_al[(size_t)MROWS * EE];
__device__ __nv_bfloat16 g_kh2[(size_t)MROWS * HKV * DD];
__device__ __nv_bfloat16 g_kl2[(size_t)MROWS * HKV * DD];
__device__ __nv_bfloat16 g_vh2[(size_t)MROWS * HKV * DD];
__device__ __nv_bfloat16 g_vl2[(size_t)MROWS * HKV * DD];
__device__ __nv_bfloat16 g_oh[(size_t)MROWS * HQ * DD];
__device__ __nv_bfloat16 g_ol[(size_t)MROWS * HQ * DD];
__device__ __nv_bfloat16 g_wqh[(size_t)(HQ*DD) * EE];
__device__ __nv_bfloat16 g_wql[(size_t)(HQ*DD) * EE];
__device__ __nv_bfloat16 g_wkh[(size_t)(HKV*DD) * EE];
__device__ __nv_bfloat16 g_wkl[(size_t)(HKV*DD) * EE];
__device__ __nv_bfloat16 g_wvh[(size_t)(HKV*DD) * EE];
__device__ __nv_bfloat16 g_wvl[(size_t)(HKV*DD) * EE];
__device__ __nv_bfloat16 g_woh[(size_t)EE * (HQ*DD)];
__device__ __nv_bfloat16 g_wol[(size_t)EE * (HQ*DD)];

// ---------------------------------------------------------------------------
// PTX helpers (base-ISA: cp.async / ldmatrix / mma.sync)
// ---------------------------------------------------------------------------
__device__ __forceinline__ uint32_t smem_u32(const void* p) {
    uint32_t a;
    asm("{ .reg .u64 t; cvta.to.shared.u64 t, %1; cvt.u32.u64 %0, t; }"
        : "=r"(a) : "l"(p));
    return a;
}

__device__ __forceinline__ void cpa16(uint32_t d, const void* s) {
    asm volatile("cp.async.cg.shared.global [%0], [%1], 16;" :: "r"(d), "l"(s));
}
#define CP_COMMIT() asm volatile("cp.async.commit_group;")
#define CP_WAIT(n)  asm volatile("cp.async.wait_group %0;" :: "n"(n))

__device__ __forceinline__ void ldmx4(uint32_t a, uint32_t r[4]) {
    asm volatile("ldmatrix.sync.aligned.m8n8.x4.shared.b16 {%0,%1,%2,%3}, [%4];"
                 : "=r"(r[0]), "=r"(r[1]), "=r"(r[2]), "=r"(r[3]) : "r"(a));
}
__device__ __forceinline__ void ldmx4t(uint32_t a, uint32_t r[4]) {
    asm volatile("ldmatrix.sync.aligned.m8n8.x4.trans.shared.b16 {%0,%1,%2,%3}, [%4];"
                 : "=r"(r[0]), "=r"(r[1]), "=r"(r[2]), "=r"(r[3]) : "r"(a));
}

__device__ __forceinline__ void mma16816(float c[4], const uint32_t a[4],
                                         const uint32_t b[2]) {
    asm volatile(
        "mma.sync.aligned.m16n8k16.row.col.f32.bf16.bf16.f32 "
        "{%0,%1,%2,%3}, {%4,%5,%6,%7}, {%8,%9}, {%0,%1,%2,%3};"
        : "+f"(c[0]), "+f"(c[1]), "+f"(c[2]), "+f"(c[3])
        : "r"(a[0]), "r"(a[1]), "r"(a[2]), "r"(a[3]), "r"(b[0]), "r"(b[1]));
}

// ---------------------------------------------------------------------------
// fused prep: z=0..3 -> transpose+split weight z; z=4 -> elementwise split X
// ---------------------------------------------------------------------------
__global__ void prep_kernel(
    const float* __restrict__ X, __nv_bfloat16* __restrict__ xh, __nv_bfloat16* __restrict__ xl,
    const float* __restrict__ W0, __nv_bfloat16* __restrict__ h0, __nv_bfloat16* __restrict__ l0,
    const float* __restrict__ W1, __nv_bfloat16* __restrict__ h1, __nv_bfloat16* __restrict__ l1,
    const float* __restrict__ W2, __nv_bfloat16* __restrict__ h2, __nv_bfloat16* __restrict__ l2,
    const float* __restrict__ W3, __nv_bfloat16* __restrict__ h3, __nv_bfloat16* __restrict__ l3)
{
    const int z = blockIdx.z;
    if (z == 4) {
        // X split: 4096x64 blocks in (x,y); each block: 512 float4
        const int blk = blockIdx.y * 64 + blockIdx.x;
        const int tid = threadIdx.y * 32 + threadIdx.x;
        const int base = blk * 512;
#pragma unroll
        for (int rep = 0; rep < 2; rep++) {
            int i = base + tid + rep * 256;
            float4 v = ((const float4*)X)[i];
            __nv_bfloat16 hh0 = __float2bfloat16(v.x);
            __nv_bfloat16 hh1 = __float2bfloat16(v.y);
            __nv_bfloat16 hh2 = __float2bfloat16(v.z);
            __nv_bfloat16 hh3 = __float2bfloat16(v.w);
            __nv_bfloat16 ll0 = __float2bfloat16(v.x - __bfloat162float(hh0));
            __nv_bfloat16 ll1 = __float2bfloat16(v.y - __bfloat162float(hh1));
            __nv_bfloat16 ll2 = __float2bfloat16(v.z - __bfloat162float(hh2));
            __nv_bfloat16 ll3 = __float2bfloat16(v.w - __bfloat162float(hh3));
            ((__nv_bfloat162*)xh)[2*i]   = __halves2bfloat162(hh0, hh1);
            ((__nv_bfloat162*)xh)[2*i+1] = __halves2bfloat162(hh2, hh3);
            ((__nv_bfloat162*)xl)[2*i]   = __halves2bfloat162(ll0, ll1);
            ((__nv_bfloat162*)xl)[2*i+1] = __halves2bfloat162(ll2, ll3);
        }
        return;
    }

    const float* W; __nv_bfloat16 *Th, *Tl; int K, N;
    switch (z) {
        case 0: W = W0; Th = h0; Tl = l0; K = EE;    N = HQ*DD;  break;
        case 1: W = W1; Th = h1; Tl = l1; K = EE;    N = HKV*DD; break;
        case 2: W = W2; Th = h2; Tl = l2; K = EE;    N = HKV*DD; break;
        default:W = W3; Th = h3; Tl = l3; K = HQ*DD; N = EE;     break;
    }
    const int n0 = blockIdx.x * 32, k0 = blockIdx.y * 32;
    if (n0 >= N || k0 >= K) return;

    __shared__ float ts[32][33];
    const int tx = threadIdx.x, ty = threadIdx.y;
    for (int i = ty; i < 32; i += 8)
        ts[i][tx] = W[(size_t)(k0 + i) * N + n0 + tx];
    __syncthreads();
    for (int i = ty; i < 32; i += 8) {
        float v = ts[tx][i];
        __nv_bfloat16 hv = __float2bfloat16(v);
        __nv_bfloat16 lv = __float2bfloat16(v - __bfloat162float(hv));
        size_t o = (size_t)(n0 + i) * K + k0 + tx;
        Th[o] = hv;
        Tl[o] = lv;
    }
}

// ---------------------------------------------------------------------------
// bf16x3 GEMM core via mma.sync. 2 CTAs/SM. Single-barrier pipeline:
//   wait(0) -> sync -> prefetch(kt+1) -> compute(kt)
// Safety: prefetch at kt targets buffer (kt+1)&1, last read at kt-1; every
// warp past kt's barrier has finished kt-1's compute.
// ---------------------------------------------------------------------------
#define BKG 32
#define SROW 80
#define TBYTES (128 * SROW)
#define BUFBYTES (4 * TBYTES)
#define GSMEM_BYTES (2 * BUFBYTES)   // 81920; epilogue reuses as 128x132 fp32

__device__ __forceinline__ void tile_cp(uint32_t sdst,
                                        const __nv_bfloat16* __restrict__ g,
                                        int ldk, int row0, int k0, int t)
{
    const char* gb = (const char*)(g + (size_t)row0 * ldk + k0);
    const size_t rs = (size_t)ldk * 2;
#pragma unroll
    for (int i = 0; i < 2; i++) {
        int idx = t + i * 256;
        int r = idx >> 2;
        int c = (idx & 3) << 4;
        cpa16(sdst + r * SROW + c, gb + (size_t)r * rs + c);
    }
}

__device__ __forceinline__ void gemm_core(
    const __nv_bfloat16* __restrict__ Ah, const __nv_bfloat16* __restrict__ Al,
    const __nv_bfloat16* __restrict__ Bh, const __nv_bfloat16* __restrict__ Bl,
    uint32_t sbase, int t, int bm, int bn, int K, float acc[4][4][4])
{
    const int lane = t & 31, wid = t >> 5;
    const int wm = wid & 1, wn = wid >> 1;
    const int NT = K / BKG;

    {
        tile_cp(sbase,              Ah, K, bm, 0, t);
        tile_cp(sbase + TBYTES,     Al, K, bm, 0, t);
        tile_cp(sbase + 2 * TBYTES, Bh, K, bn, 0, t);
        tile_cp(sbase + 3 * TBYTES, Bl, K, bn, 0, t);
        CP_COMMIT();
    }

    const int q = lane >> 3, r8 = lane & 7;
    const int arow = wm * 64 + (q & 1) * 8 + r8;
    const int acolb = ((q >> 1) * 8) * 2;
    const int t16 = lane & 15;
    const int b4row = wn * 32 + (t16 & 7) + ((lane >> 4) * 8);
    const int b4colb = (t16 >> 3) * 16;

    for (int kt = 0; kt < NT; kt++) {
        const uint32_t sb = sbase + (kt & 1) * BUFBYTES;
        CP_WAIT(0);
        __syncthreads();
        if (kt + 1 < NT) {
            const uint32_t sn = sbase + ((kt + 1) & 1) * BUFBYTES;
            const int k0 = (kt + 1) * BKG;
            tile_cp(sn,              Ah, K, bm, k0, t);
            tile_cp(sn + TBYTES,     Al, K, bm, k0, t);
            tile_cp(sn + 2 * TBYTES, Bh, K, bn, k0, t);
            tile_cp(sn + 3 * TBYTES, Bl, K, bn, k0, t);
            CP_COMMIT();
        }

#pragma unroll
        for (int kk = 0; kk < 2; kk++) {
            const uint32_t abase = sb + arow * SROW + kk * 32 + acolb;
            const uint32_t bbase = sb + 2 * TBYTES + b4row * SROW + kk * 32 + b4colb;
            uint32_t bh_[4][2], bl_[4][2];
#pragma unroll
            for (int ntp = 0; ntp < 2; ntp++) {
                uint32_t r4[4];
                ldmx4(bbase + ntp * 16 * SROW, r4);
                bh_[2*ntp][0] = r4[0]; bh_[2*ntp][1] = r4[1];
                bh_[2*ntp+1][0] = r4[2]; bh_[2*ntp+1][1] = r4[3];
                ldmx4(bbase + TBYTES + ntp * 16 * SROW, r4);
                bl_[2*ntp][0] = r4[0]; bl_[2*ntp][1] = r4[1];
                bl_[2*ntp+1][0] = r4[2]; bl_[2*ntp+1][1] = r4[3];
            }
#pragma unroll
            for (int mt = 0; mt < 4; mt++) {
                uint32_t ah_[4], al_[4];
                ldmx4(abase + mt * 16 * SROW, ah_);
                ldmx4(abase + TBYTES + mt * 16 * SROW, al_);
#pragma unroll
                for (int nt = 0; nt < 4; nt++) {
                    mma16816(acc[mt][nt], ah_, bh_[nt]);
                    mma16816(acc[mt][nt], ah_, bl_[nt]);
                    mma16816(acc[mt][nt], al_, bh_[nt]);
                }
            }
        }
    }
    __syncthreads();   // protect smem before epilogue reuse
}

// ---------------------------------------------------------------------------
// Fused QKV projection with RoPE in the epilogue. 1D grid of 640 CTAs.
// ---------------------------------------------------------------------------
__global__ __launch_bounds__(256, 2)
void gemm_qkv(const __nv_bfloat16* __restrict__ Ah,
              const __nv_bfloat16* __restrict__ Al,
              const __nv_bfloat16* __restrict__ BhQ, const __nv_bfloat16* __restrict__ BlQ,
              const float* __restrict__ bQ,
              __nv_bfloat16* __restrict__ QH, __nv_bfloat16* __restrict__ QL,
              const __nv_bfloat16* __restrict__ BhK, const __nv_bfloat16* __restrict__ BlK,
              const float* __restrict__ bK,
              __nv_bfloat16* __restrict__ KH, __nv_bfloat16* __restrict__ KL,
              const __nv_bfloat16* __restrict__ BhV, const __nv_bfloat16* __restrict__ BlV,
              const float* __restrict__ bV,
              __nv_bfloat16* __restrict__ VH, __nv_bfloat16* __restrict__ VL,
              float qscale)
{
    extern __shared__ char sm[];
    const uint32_t sbase = smem_u32(sm);
    const int t = threadIdx.x;
    const int wid = t >> 5, lane = t & 31;
    const int wm = wid & 1, wn = wid >> 1;
    const int bid = blockIdx.x;

    const __nv_bfloat16 *Bh, *Bl;
    const float* bias;
    __nv_bfloat16 *OH, *OL;
    int bm, bn, N;
    int rope;
    float oscale;
    if (bid < 512) {
        Bh = BhQ; Bl = BlQ; bias = bQ; OH = QH; OL = QL;
        bn = (bid & 15) * 128; bm = (bid >> 4) * 128;
        N = HQ * DD; rope = 1; oscale = qscale;
    } else if (bid < 576) {
        int idx = bid - 512;
        Bh = BhK; Bl = BlK; bias = bK; OH = KH; OL = KL;
        bn = (idx & 1) * 128; bm = (idx >> 1) * 128;
        N = HKV * DD; rope = 1; oscale = 1.0f;
    } else {
        int idx = bid - 576;
        Bh = BhV; Bl = BlV; bias = bV; OH = VH; OL = VL;
        bn = (idx & 1) * 128; bm = (idx >> 1) * 128;
        N = HKV * DD; rope = 0; oscale = 1.0f;
    }

    float acc[4][4][4];
#pragma unroll
    for (int mt = 0; mt < 4; mt++)
#pragma unroll
        for (int nt = 0; nt < 4; nt++)
#pragma unroll
            for (int i = 0; i < 4; i++) acc[mt][nt][i] = 0.f;

    gemm_core(Ah, Al, Bh, Bl, sbase, t, bm, bn, EE, acc);

    const int gid = lane >> 2, tid2 = (lane & 3) * 2;

    if (!rope) {
#pragma unroll
        for (int mt = 0; mt < 4; mt++) {
            const int row = bm + wm * 64 + mt * 16 + gid;
#pragma unroll
            for (int nt = 0; nt < 4; nt++) {
                const int col = bn + wn * 32 + nt * 8 + tid2;
                const float b0 = bias[col], b1 = bias[col + 1];
                float v0 = acc[mt][nt][0] + b0, v1 = acc[mt][nt][1] + b1;
                float v2 = acc[mt][nt][2] + b0, v3 = acc[mt][nt][3] + b1;
                __nv_bfloat162 h0 = __floats2bfloat162_rn(v0, v1);
                __nv_bfloat162 l0 = __floats2bfloat162_rn(
                    v0 - __bfloat162float(h0.x), v1 - __bfloat162float(h0.y));
                __nv_bfloat162 h1 = __floats2bfloat162_rn(v2, v3);
                __nv_bfloat162 l1 = __floats2bfloat162_rn(
                    v2 - __bfloat162float(h1.x), v3 - __bfloat162float(h1.y));
                *(__nv_bfloat162*)&OH[(size_t)row * N + col] = h0;
                *(__nv_bfloat162*)&OL[(size_t)row * N + col] = l0;
                *(__nv_bfloat162*)&OH[(size_t)(row + 8) * N + col] = h1;
                *(__nv_bfloat162*)&OL[(size_t)(row + 8) * N + col] = l1;
            }
        }
        return;
    }

    // Q/K: stage fp32 tile (bias added) in smem, then rope + split + store.
    float* sf = (float*)sm;   // [128][132]
#pragma unroll
    for (int mt = 0; mt < 4; mt++) {
        const int rl0 = wm * 64 + mt * 16 + gid;
#pragma unroll
        for (int nt = 0; nt < 4; nt++) {
            const int cl = wn * 32 + nt * 8 + tid2;
            const float b0 = bias[bn + cl], b1 = bias[bn + cl + 1];
            *(float2*)&sf[rl0 * 132 + cl] =
                make_float2(acc[mt][nt][0] + b0, acc[mt][nt][1] + b1);
            *(float2*)&sf[(rl0 + 8) * 132 + cl] =
                make_float2(acc[mt][nt][2] + b0, acc[mt][nt][3] + b1);
        }
    }
    __syncthreads();

    float invf[8];
#pragma unroll
    for (int nt = 0; nt < 4; nt++) {
        int c0 = (wn * 32 + nt * 8 + tid2) & 63;
        invf[2*nt]     = powf(1000000.0f, -(float)(2 * c0) * (1.0f / 128.0f));
        invf[2*nt + 1] = powf(1000000.0f, -(float)(2 * (c0 + 1)) * (1.0f / 128.0f));
    }

#pragma unroll
    for (int mt = 0; mt < 4; mt++) {
#pragma unroll
        for (int half = 0; half < 2; half++) {
            const int rl = wm * 64 + mt * 16 + gid + half * 8;
            const int rowg = bm + rl;
            const float pos = (float)(rowg & (LL - 1));
#pragma unroll
            for (int nt = 0; nt < 4; nt++) {
                const int cl = wn * 32 + nt * 8 + tid2;
                float2 v = *(float2*)&sf[rl * 132 + cl];
                float2 p = *(float2*)&sf[rl * 132 + (cl ^ 64)];
                float a0 = pos * invf[2*nt], a1 = pos * invf[2*nt + 1];
                float c0 = cosf(a0), s0 = sinf(a0);
                float c1 = cosf(a1), s1 = sinf(a1);
                float y0, y1;
                if (cl < 64) {
                    y0 = v.x * c0 - p.x * s0;
                    y1 = v.y * c1 - p.y * s1;
                } else {
                    y0 = v.x * c0 + p.x * s0;
                    y1 = v.y * c1 + p.y * s1;
                }
                y0 *= oscale; y1 *= oscale;
                __nv_bfloat162 h = __floats2bfloat162_rn(y0, y1);
                __nv_bfloat162 lo = __floats2bfloat162_rn(
                    y0 - __bfloat162float(h.x), y1 - __bfloat162float(h.y));
                *(__nv_bfloat162*)&OH[(size_t)rowg * N + bn + cl] = h;
                *(__nv_bfloat162*)&OL[(size_t)rowg * N + bn + cl] = lo;
            }
        }
    }
}

// O projection (fp32 out, no bias)
__global__ __launch_bounds__(256, 2)
void gemm_bf16x3(const __nv_bfloat16* __restrict__ Ah,
                 const __nv_bfloat16* __restrict__ Al,
                 const __nv_bfloat16* __restrict__ Bh,
                 const __nv_bfloat16* __restrict__ Bl,
                 float* __restrict__ C, int M, int N, int K)
{
    extern __shared__ char sm[];
    const uint32_t sbase = smem_u32(sm);
    const int t = threadIdx.x;
    const int wid = t >> 5, lane = t & 31;
    const int wm = wid & 1, wn = wid >> 1;
    const int bm = blockIdx.y * 128, bn = blockIdx.x * 128;

    float acc[4][4][4];
#pragma unroll
    for (int mt = 0; mt < 4; mt++)
#pragma unroll
        for (int nt = 0; nt < 4; nt++)
#pragma unroll
            for (int i = 0; i < 4; i++) acc[mt][nt][i] = 0.f;

    gemm_core(Ah, Al, Bh, Bl, sbase, t, bm, bn, K, acc);

    const int gid = lane >> 2, tid2 = (lane & 3) * 2;
#pragma unroll
    for (int mt = 0; mt < 4; mt++) {
        const int row = bm + wm * 64 + mt * 16 + gid;
#pragma unroll
        for (int nt = 0; nt < 4; nt++) {
            const int col = bn + wn * 32 + nt * 8 + tid2;
            *(float2*)&C[(size_t)row * N + col] =
                make_float2(acc[mt][nt][0], acc[mt][nt][1]);
            *(float2*)&C[(size_t)(row + 8) * N + col] =
                make_float2(acc[mt][nt][2], acc[mt][nt][3]);
        }
    }
}

// ---------------------------------------------------------------------------
// Flash attention on tensor cores (mma.sync bf16x3), causal, GQA G=8.
// Single-barrier pipeline per kv-tile: wait(0) -> sync -> prefetch -> compute.
// ---------------------------------------------------------------------------
#define KROW 272
#define ATILE (64 * KROW)
#define ABUF  (4 * ATILE)
#define ASMEM (2 * ABUF)

__global__ __launch_bounds__(256)
void attn_mma(const __nv_bfloat16* __restrict__ Qh,
              const __nv_bfloat16* __restrict__ Ql,
              const __nv_bfloat16* __restrict__ Kh,
              const __nv_bfloat16* __restrict__ Kl,
              const __nv_bfloat16* __restrict__ Vh,
              const __nv_bfloat16* __restrict__ Vl,
              __nv_bfloat16* __restrict__ Oh,
              __nv_bfloat16* __restrict__ Ol)
{
    extern __shared__ char sm[];
    const uint32_t sb = smem_u32(sm);
    const int t = threadIdx.x, w = t >> 5, lane = t & 31;
    const int bid = blockIdx.x;
    const int qt = 15 - (bid >> 5);
    const int bh = bid & 31;
    const int b = bh >> 4, h = bh & 15, hk = h >> 3;
    const int q0 = qt * 128;

    {
        const char* gqh = (const char*)(Qh + ((size_t)(b * LL + q0)) * (HQ * DD) + h * DD);
        const char* gql = (const char*)(Ql + ((size_t)(b * LL + q0)) * (HQ * DD) + h * DD);
#pragma unroll
        for (int i = 0; i < 8; i++) {
            int idx = t + i * 256;
            int r = idx >> 4;
            int c = (idx & 15) << 4;
            cpa16(sb + r * KROW + c,               gqh + (size_t)r * 4096 + c);
            cpa16(sb + 128 * KROW + r * KROW + c,  gql + (size_t)r * 4096 + c);
        }
        CP_COMMIT();
        CP_WAIT(0);
        __syncthreads();
    }

    uint32_t qfh[8][4], qfl[8][4];
    {
        const int qq = lane >> 3, r8 = lane & 7;
        const uint32_t qaddr = sb + (w * 16 + (qq & 1) * 8 + r8) * KROW + (qq >> 1) * 16;
#pragma unroll
        for (int c = 0; c < 8; c++) {
            ldmx4(qaddr + c * 32, qfh[c]);
            ldmx4(qaddr + 128 * KROW + c * 32, qfl[c]);
        }
    }
    __syncthreads();

    float oacc[16][4];
#pragma unroll
    for (int v = 0; v < 16; v++)
#pragma unroll
        for (int e = 0; e < 4; e++) oacc[v][e] = 0.f;
    float m0 = -1e30f, m1 = -1e30f, l0 = 0.f, l1 = 0.f;

    const int NT = 2 * qt + 2;
    const size_t kvrow = (size_t)(HKV * DD) * 2;

    // prologue: prefetch kv tile 0 -> buffer 0
    {
        const size_t roff = ((size_t)(b * LL)) * (HKV * DD) + hk * DD;
        const char* srcs[4] = {(const char*)(Kh + roff), (const char*)(Kl + roff),
                               (const char*)(Vh + roff), (const char*)(Vl + roff)};
#pragma unroll
        for (int i = 0; i < 16; i++) {
            int idx = t + i * 256;
            int mat = idx >> 10;
            int r = (idx >> 4) & 63;
            int c = (idx & 15) << 4;
            cpa16(sb + mat * ATILE + r * KROW + c, srcs[mat] + (size_t)r * kvrow + c);
        }
        CP_COMMIT();
    }

    const int g = lane >> 2;
    const int row0 = q0 + w * 16 + g;
    const int colq = (lane & 3) * 2;

    for (int kt = 0; kt < NT; kt++) {
        CP_WAIT(0);
        __syncthreads();
        if (kt + 1 < NT) {
            const uint32_t nb = sb + ((kt + 1) & 1) * ABUF;
            const size_t roff = ((size_t)(b * LL + (kt + 1) * 64)) * (HKV * DD) + hk * DD;
            const char* srcs[4] = {(const char*)(Kh + roff), (const char*)(Kl + roff),
                                   (const char*)(Vh + roff), (const char*)(Vl + roff)};
#pragma unroll
            for (int i = 0; i < 16; i++) {
                int idx = t + i * 256;
                int mat = idx >> 10;
                int r = (idx >> 4) & 63;
                int c = (idx & 15) << 4;
                cpa16(nb + mat * ATILE + r * KROW + c, srcs[mat] + (size_t)r * kvrow + c);
            }
            CP_COMMIT();
        }

        const uint32_t kb = sb + (kt & 1) * ABUF;
        const int kv0 = kt * 64;

        float s_[8][4];
#pragma unroll
        for (int j = 0; j < 8; j++)
#pragma unroll
            for (int e = 0; e < 4; e++) s_[j][e] = 0.f;

        const uint32_t kaddr = kb + (lane & 7) * KROW + (lane >> 3) * 16;
#pragma unroll
        for (int c32 = 0; c32 < 4; c32++) {
#pragma unroll
            for (int j = 0; j < 8; j++) {
                uint32_t kfh[4], kfl[4];
                ldmx4(kaddr + j * 8 * KROW + c32 * 64, kfh);
                ldmx4(kaddr + ATILE + j * 8 * KROW + c32 * 64, kfl);
                uint32_t bh0[2] = {kfh[0], kfh[1]}, bh1[2] = {kfh[2], kfh[3]};
                uint32_t bl0[2] = {kfl[0], kfl[1]}, bl1[2] = {kfl[2], kfl[3]};
                mma16816(s_[j], qfh[2 * c32],     bh0);
                mma16816(s_[j], qfh[2 * c32 + 1], bh1);
                mma16816(s_[j], qfh[2 * c32],     bl0);
                mma16816(s_[j], qfh[2 * c32 + 1], bl1);
                mma16816(s_[j], qfl[2 * c32],     bh0);
                mma16816(s_[j], qfl[2 * c32 + 1], bh1);
            }
        }

#pragma unroll
        for (int j = 0; j < 8; j++) {
            int c0 = kv0 + 8 * j + colq;
            if (c0 > row0)     s_[j][0] = -1e30f;
            if (c0 + 1 > row0) s_[j][1] = -1e30f;
            if (c0 > row0 + 8)     s_[j][2] = -1e30f;
            if (c0 + 1 > row0 + 8) s_[j][3] = -1e30f;
        }

        float mx0 = -1e30f, mx1 = -1e30f;
#pragma unroll
        for (int j = 0; j < 8; j++) {
            mx0 = fmaxf(mx0, fmaxf(s_[j][0], s_[j][1]));
            mx1 = fmaxf(mx1, fmaxf(s_[j][2], s_[j][3]));
        }
        mx0 = fmaxf(mx0, __shfl_xor_sync(0xffffffffu, mx0, 1));
        mx0 = fmaxf(mx0, __shfl_xor_sync(0xffffffffu, mx0, 2));
        mx1 = fmaxf(mx1, __shfl_xor_sync(0xffffffffu, mx1, 1));
        mx1 = fmaxf(mx1, __shfl_xor_sync(0xffffffffu, mx1, 2));
        const float m0n = fmaxf(m0, mx0), m1n = fmaxf(m1, mx1);
        const float cr0 = __expf(m0 - m0n), cr1 = __expf(m1 - m1n);
        float sum0 = 0.f, sum1 = 0.f;
#pragma unroll
        for (int j = 0; j < 8; j++) {
            s_[j][0] = __expf(s_[j][0] - m0n); sum0 += s_[j][0];
            s_[j][1] = __expf(s_[j][1] - m0n); sum0 += s_[j][1];
            s_[j][2] = __expf(s_[j][2] - m1n); sum1 += s_[j][2];
            s_[j][3] = __expf(s_[j][3] - m1n); sum1 += s_[j][3];
        }
        sum0 += __shfl_xor_sync(0xffffffffu, sum0, 1);
        sum0 += __shfl_xor_sync(0xffffffffu, sum0, 2);
        sum1 += __shfl_xor_sync(0xffffffffu, sum1, 1);
        sum1 += __shfl_xor_sync(0xffffffffu, sum1, 2);
        l0 = l0 * cr0 + sum0;  m0 = m0n;
        l1 = l1 * cr1 + sum1;  m1 = m1n;
#pragma unroll
        for (int v = 0; v < 16; v++) {
            oacc[v][0] *= cr0; oacc[v][1] *= cr0;
            oacc[v][2] *= cr1; oacc[v][3] *= cr1;
        }

        // ---- O += P V (bf16x3); P packed per-t32 ----
        const uint32_t vaddr = kb + 2 * ATILE + lane * KROW;
#pragma unroll
        for (int t32 = 0; t32 < 2; t32++) {
            uint32_t Ah0[4], Ah1[4], Al0[4], Al1[4];
#pragma unroll
            for (int u = 0; u < 4; u++) {
                const int j = 4 * t32 + u;
                __nv_bfloat162 h01 = __floats2bfloat162_rn(s_[j][0], s_[j][1]);
                __nv_bfloat162 h23 = __floats2bfloat162_rn(s_[j][2], s_[j][3]);
                __nv_bfloat162 lo01 = __floats2bfloat162_rn(
                    s_[j][0] - __bfloat162float(h01.x),
                    s_[j][1] - __bfloat162float(h01.y));
                __nv_bfloat162 lo23 = __floats2bfloat162_rn(
                    s_[j][2] - __bfloat162float(h23.x),
                    s_[j][3] - __bfloat162float(h23.y));
                uint32_t* Ahp = (u < 2) ? Ah0 : Ah1;
                uint32_t* Alp = (u < 2) ? Al0 : Al1;
                const int base = (u & 1) * 2;
                Ahp[base]     = *(uint32_t*)&h01;
                Ahp[base + 1] = *(uint32_t*)&h23;
                Alp[base]     = *(uint32_t*)&lo01;
                Alp[base + 1] = *(uint32_t*)&lo23;
            }
#pragma unroll
            for (int v = 0; v < 16; v++) {
                uint32_t vfh[4], vfl[4];
                ldmx4t(vaddr + t32 * 32 * KROW + v * 16, vfh);
                ldmx4t(vaddr + ATILE + t32 * 32 * KROW + v * 16, vfl);
                uint32_t bh0[2] = {vfh[0], vfh[1]}, bh1[2] = {vfh[2], vfh[3]};
                uint32_t bl0[2] = {vfl[0], vfl[1]}, bl1[2] = {vfl[2], vfl[3]};
                mma16816(oacc[v], Ah0, bh0);
                mma16816(oacc[v], Ah1, bh1);
                mma16816(oacc[v], Ah0, bl0);
                mma16816(oacc[v], Ah1, bl1);
                mma16816(oacc[v], Al0, bh0);
                mma16816(oacc[v], Al1, bh1);
            }
        }
    }

    const float inv0 = 1.0f / l0, inv1 = 1.0f / l1;
    const size_t r0off = ((size_t)(b * LL + q0 + w * 16 + g)) * (HQ * DD) + h * DD + colq;
    const size_t r1off = r0off + 8 * (size_t)(HQ * DD);
#pragma unroll
    for (int v = 0; v < 16; v++) {
        float a0 = oacc[v][0] * inv0, a1 = oacc[v][1] * inv0;
        float a2 = oacc[v][2] * inv1, a3 = oacc[v][3] * inv1;
        __nv_bfloat162 h0 = __floats2bfloat162_rn(a0, a1);
        __nv_bfloat162 lo0 = __floats2bfloat162_rn(
            a0 - __bfloat162float(h0.x), a1 - __bfloat162float(h0.y));
        __nv_bfloat162 h1 = __floats2bfloat162_rn(a2, a3);
        __nv_bfloat162 lo1 = __floats2bfloat162_rn(
            a2 - __bfloat162float(h1.x), a3 - __bfloat162float(h1.y));
        *(__nv_bfloat162*)&Oh[r0off + 8 * v] = h0;
        *(__nv_bfloat162*)&Ol[r0off + 8 * v] = lo0;
        *(__nv_bfloat162*)&Oh[r1off + 8 * v] = h1;
        *(__nv_bfloat162*)&Ol[r1off + 8 * v] = lo1;
    }
}

// ---------------------------------------------------------------------------
// Launch
// ---------------------------------------------------------------------------
extern "C" void kernel_launch(void* const* d_in, const int* in_sizes, int n_in,
                              void* d_out, int out_size)
{
    const float* X  = (const float*)d_in[0];
    const float* Wq = (const float*)d_in[1];
    const float* bq = (const float*)d_in[2];
    const float* Wk = (const float*)d_in[3];
    const float* bk = (const float*)d_in[4];
    const float* Wv = (const float*)d_in[5];
    const float* bv = (const float*)d_in[6];
    const float* Wo = (const float*)d_in[7];
    float* out = (float*)d_out;

    __nv_bfloat16 *ah, *al, *kh2, *kl2, *vh2, *vl2, *oh, *ol;
    __nv_bfloat16 *wqh, *wql, *wkh, *wkl, *wvh, *wvl, *woh, *wol;
    cudaGetSymbolAddress((void**)&ah, g_ah);
    cudaGetSymbolAddress((void**)&al, g_al);
    cudaGetSymbolAddress((void**)&kh2, g_kh2);
    cudaGetSymbolAddress((void**)&kl2, g_kl2);
    cudaGetSymbolAddress((void**)&vh2, g_vh2);
    cudaGetSymbolAddress((void**)&vl2, g_vl2);
    cudaGetSymbolAddress((void**)&oh, g_oh);
    cudaGetSymbolAddress((void**)&ol, g_ol);
    cudaGetSymbolAddress((void**)&wqh, g_wqh);
    cudaGetSymbolAddress((void**)&wql, g_wql);
    cudaGetSymbolAddress((void**)&wkh, g_wkh);
    cudaGetSymbolAddress((void**)&wkl, g_wkl);
    cudaGetSymbolAddress((void**)&wvh, g_wvh);
    cudaGetSymbolAddress((void**)&wvl, g_wvl);
    cudaGetSymbolAddress((void**)&woh, g_woh);
    cudaGetSymbolAddress((void**)&wol, g_wol);

    cudaFuncSetAttribute(gemm_qkv,
                         cudaFuncAttributeMaxDynamicSharedMemorySize, GSMEM_BYTES);
    cudaFuncSetAttribute(gemm_bf16x3,
                         cudaFuncAttributeMaxDynamicSharedMemorySize, GSMEM_BYTES);
    cudaFuncSetAttribute(attn_mma,
                         cudaFuncAttributeMaxDynamicSharedMemorySize, ASMEM);

    const float scale = 0.08838834764831845f;   // 1/sqrt(128)

    // One prep launch: X split (z=4) + all 4 weight transpose/splits (z=0..3)
    prep_kernel<<<dim3(64, 64, 5), dim3(32, 8)>>>(
        X, ah, al,
        Wq, wqh, wql, Wk, wkh, wkl, Wv, wvh, wvl, Wo, woh, wol);

    // Fused Q+K+V projections with rope+split epilogue (Q -> oh/ol)
    gemm_qkv<<<640, 256, GSMEM_BYTES>>>(
        ah, al,
        wqh, wql, bq, oh, ol,
        wkh, wkl, bk, kh2, kl2,
        wvh, wvl, bv, vh2, vl2,
        scale);

    // Attention: Q from oh/ol, output -> ah/al (X splits dead now)
    attn_mma<<<512, 256, ASMEM>>>(
        oh, ol, kh2, kl2, vh2, vl2, ah, al);

    // Output projection reads ah/al
    gemm_bf16x3<<<dim3(EE/128, MROWS/128), 256, GSMEM_BYTES>>>(
        ah, al, woh, wol, out, MROWS, EE, EE);
}